// round 5
// baseline (speedup 1.0000x reference)
#include <cuda_runtime.h>
#include <cuda_bf16.h>
#include <cstdint>

#define NUM_SPECIES 7
#define BMOL 1024
#define NA 48
#define NATOMS (BMOL * NA)   /* 49152 */
#define FDIM 384
#define TILE_M 32
#define NTHREADS 256

/* layer sizes */
#define N1 256
#define N2 192
#define N3 160
#define K1 384
#define K2 256
#define K3 192

#define W1_ELEMS (NUM_SPECIES * N1 * K1)
#define W2_ELEMS (NUM_SPECIES * N2 * K2)
#define W3_ELEMS (NUM_SPECIES * N3 * K3)
#define W_OFF1 0
#define W_OFF2 (W1_ELEMS)
#define W_OFF3 (W1_ELEMS + W2_ELEMS)
#define W_TOTAL (W1_ELEMS + W2_ELEMS + W3_ELEMS)

__device__ int   g_counts[NUM_SPECIES];
__device__ int   g_lists[NUM_SPECIES * NATOMS];
__device__ float g_atom_energy[NATOMS];
__device__ __align__(16) __nv_bfloat16 g_wh[W_TOTAL];
__device__ __align__(16) __nv_bfloat16 g_wl[W_TOTAL];

/* ---------------- SMEM byte offsets (total 98432 -> 2 CTAs/SM) ----------- */
#define R0_HI 0          /* 32 x 768B */
#define R0_LO 24576
#define R1_HI 49152      /* 32 x 512B */
#define R1_LO 65536
#define WBUF  81920      /* 2 buffers x 8KB; row = [hi 64B | lo 64B] swizzled */
#define SIDX  98304
#define SMEM_TOTAL 98432

/* ---------------- PTX helpers ------------------------------------------- */
__device__ __forceinline__ uint32_t smem_u32(const void* p) {
    uint32_t a;
    asm("{ .reg .u64 t; cvta.to.shared.u64 t, %1; cvt.u32.u64 %0, t; }" : "=r"(a) : "l"(p));
    return a;
}
__device__ __forceinline__ void cp16(uint32_t dst, const void* src) {
    asm volatile("cp.async.ca.shared.global [%0], [%1], 16;" :: "r"(dst), "l"(src));
}
#define CP_COMMIT() asm volatile("cp.async.commit_group;" ::: "memory")
#define CP_WAIT1()  asm volatile("cp.async.wait_group 1;" ::: "memory")

__device__ __forceinline__ void ldsm4(uint32_t (&r)[4], uint32_t a) {
    asm volatile("ldmatrix.sync.aligned.m8n8.x4.shared.b16 {%0,%1,%2,%3}, [%4];"
        : "=r"(r[0]), "=r"(r[1]), "=r"(r[2]), "=r"(r[3]) : "r"(a));
}
__device__ __forceinline__ void mma16816(float (&c)[4], const uint32_t (&a)[4],
                                         uint32_t b0, uint32_t b1) {
    asm volatile("mma.sync.aligned.m16n8k16.row.col.f32.bf16.bf16.f32 "
        "{%0,%1,%2,%3},{%4,%5,%6,%7},{%8,%9},{%0,%1,%2,%3};"
        : "+f"(c[0]), "+f"(c[1]), "+f"(c[2]), "+f"(c[3])
        : "r"(a[0]), "r"(a[1]), "r"(a[2]), "r"(a[3]), "r"(b0), "r"(b1));
}

/* swizzled byte offset of (row r, byte-in-row kb); rowb multiple of 128 */
__device__ __forceinline__ uint32_t swoff(uint32_t r, uint32_t kb, uint32_t rowb) {
    return r * rowb + (kb & ~127u) + ((((kb >> 4) ^ r) & 7u) << 4) + (kb & 15u);
}

__device__ __forceinline__ void split2(float a, float b, uint32_t& hp, uint32_t& lp) {
    __nv_bfloat16 ha = __float2bfloat16(a), hb = __float2bfloat16(b);
    __nv_bfloat16 la = __float2bfloat16(a - __bfloat162float(ha));
    __nv_bfloat16 lb = __float2bfloat16(b - __bfloat162float(hb));
    hp = ((uint32_t)__bfloat16_as_ushort(hb) << 16) | __bfloat16_as_ushort(ha);
    lp = ((uint32_t)__bfloat16_as_ushort(lb) << 16) | __bfloat16_as_ushort(la);
}
__device__ __forceinline__ float celu01(float x) {
    return x > 0.f ? x : 0.1f * (__expf(10.f * x) - 1.f);
}

/* ---------------- prep / bucket ----------------------------------------- */
__global__ void prep_split_kernel(const float* __restrict__ W1,
                                  const float* __restrict__ W2,
                                  const float* __restrict__ W3) {
    int i = blockIdx.x * blockDim.x + threadIdx.x;
    if (i >= W_TOTAL) return;
    float v;
    if (i < W_OFF2)      v = W1[i - W_OFF1];
    else if (i < W_OFF3) v = W2[i - W_OFF2];
    else                 v = W3[i - W_OFF3];
    __nv_bfloat16 h = __float2bfloat16(v);
    g_wh[i] = h;
    g_wl[i] = __float2bfloat16(v - __bfloat162float(h));
}
__global__ void zero_kernel() { if (threadIdx.x < NUM_SPECIES) g_counts[threadIdx.x] = 0; }
__global__ void bucket_kernel(const int* __restrict__ species) {
    int i = blockIdx.x * blockDim.x + threadIdx.x;
    if (i < NATOMS) {
        int s = species[i];
        g_lists[s * NATOMS + atomicAdd(&g_counts[s], 1)] = i;
    }
}

/* ---------------- one MLP layer on tensor cores ------------------------- */
/* out[32, N] = celu(in[32, K] * W[N, K]^T + bias); warp grid 2(M) x 4(N)   */
/* W chunks are 32-k wide; smem row = [hi 64B | lo 64B], 8-slot XOR swizzle */
template<int K, int N, int RIN, int ROUT>
__device__ __forceinline__ void mlp_layer(
    char* smem, uint32_t smb,
    uint32_t IN_HI, uint32_t IN_LO, uint32_t OUT_HI, uint32_t OUT_LO,
    const __nv_bfloat16* __restrict__ Wh, const __nv_bfloat16* __restrict__ Wl,
    const float* __restrict__ bias)
{
    const int tid = threadIdx.x;
    const int lane = tid & 31, wid = tid >> 5;
    const int wm = wid & 1, wn = wid >> 1;       /* 2 x 4 warps */
    constexpr int NK = K / 32;

    const uint32_t lrow = (uint32_t)((lane & 7) + (lane & 8)); /* 0..15 */
    const uint32_t lk   = (uint32_t)(lane >> 4);               /* 0 / 1  */
    const uint32_t arow = (uint32_t)(wm * 16) + lrow;
    const uint32_t wrow = (uint32_t)(wn * 16) + lrow;

    for (int n0 = 0; n0 < N; n0 += 64) {
        const int nsz = (N - n0 < 64) ? (N - n0) : 64;   /* 64 or 32 */
        const bool active = (wn * 16) < nsz;

        /* stage weight chunk kcc (32 k) into buffer buf */
        auto stage = [&](int kcc, int buf) {
            uint32_t wb = smb + WBUF + (uint32_t)buf * 8192u;
            for (int it = tid; it < nsz * 8; it += NTHREADS) {
                int rr = it >> 3, cc = it & 7;
                const __nv_bfloat16* src = (cc < 4)
                    ? Wh + (size_t)(n0 + rr) * K + kcc * 32 + cc * 8
                    : Wl + (size_t)(n0 + rr) * K + kcc * 32 + (cc - 4) * 8;
                cp16(wb + (uint32_t)(rr * 128 + ((cc ^ (rr & 7)) << 4)), src);
            }
        };

        stage(0, 0); CP_COMMIT();
        stage(1, 1); CP_COMMIT();

        float acc[2][4];
#pragma unroll
        for (int b = 0; b < 2; b++)
#pragma unroll
            for (int c = 0; c < 4; c++) acc[b][c] = 0.f;

        for (int kc = 0; kc < NK; kc++) {
            CP_WAIT1();
            __syncthreads();
            const uint32_t wb = smb + WBUF + (uint32_t)(kc & 1) * 8192u;
            if (active) {
                uint32_t ah[2][4], al[2][4], wh[2][4], wl[2][4];
                auto frag_load = [&](int k16, int slot) {
                    /* A: k-bytes within row */
                    uint32_t kb = (uint32_t)(kc * 64 + k16 * 32) + lk * 16u;
                    uint32_t a = swoff(arow, kb, RIN);
                    ldsm4(ah[slot], smb + IN_HI + a);
                    ldsm4(al[slot], smb + IN_LO + a);
                    /* W: column slot 0..3 = k16*2 + lk (hi), +4 (lo) */
                    uint32_t ch = (uint32_t)(k16 * 2) + lk;
                    uint32_t oh = wrow * 128 + (((ch ^ (wrow & 7u))) << 4);
                    uint32_t ol = wrow * 128 + ((((ch + 4) ^ (wrow & 7u))) << 4);
                    ldsm4(wh[slot], wb + oh);
                    ldsm4(wl[slot], wb + ol);
                };
                frag_load(0, 0);
#pragma unroll
                for (int k16 = 0; k16 < 2; k16++) {
                    const int cur = k16;
                    if (k16 < 1) frag_load(1, 1);
#pragma unroll
                    for (int nt = 0; nt < 2; nt++) {
                        mma16816(acc[nt], ah[cur], wh[cur][nt], wh[cur][nt + 2]);
                        mma16816(acc[nt], ah[cur], wl[cur][nt], wl[cur][nt + 2]);
                        mma16816(acc[nt], al[cur], wh[cur][nt], wh[cur][nt + 2]);
                    }
                }
            }
            __syncthreads();
            if (kc + 2 < NK) stage(kc + 2, kc & 1);
            CP_COMMIT();
        }

        /* epilogue: bias + celu + split -> OUT region */
        if (active) {
#pragma unroll
            for (int nt = 0; nt < 2; nt++) {
                uint32_t r0 = (uint32_t)(wm * 16 + (lane >> 2));
                int c = n0 + wn * 16 + nt * 8 + 2 * (lane & 3);
                float b0 = __ldg(bias + c), b1 = __ldg(bias + c + 1);
                float v00 = celu01(acc[nt][0] + b0);
                float v01 = celu01(acc[nt][1] + b1);
                float v10 = celu01(acc[nt][2] + b0);
                float v11 = celu01(acc[nt][3] + b1);
                uint32_t hp, lp;
                uint32_t o0 = swoff(r0, (uint32_t)(2 * c), ROUT);
                split2(v00, v01, hp, lp);
                *(uint32_t*)(smem + OUT_HI + o0) = hp;
                *(uint32_t*)(smem + OUT_LO + o0) = lp;
                uint32_t o1 = swoff(r0 + 8, (uint32_t)(2 * c), ROUT);
                split2(v10, v11, hp, lp);
                *(uint32_t*)(smem + OUT_HI + o1) = hp;
                *(uint32_t*)(smem + OUT_LO + o1) = lp;
            }
        }
    }
    __syncthreads();
}

/* ---------------- main kernel ------------------------------------------- */
__global__ void __launch_bounds__(NTHREADS, 2)
mlp_kernel(const float* __restrict__ aev,
           const float* __restrict__ b1, const float* __restrict__ b2,
           const float* __restrict__ b3,
           const float* __restrict__ W4, const float* __restrict__ b4)
{
    const int s = blockIdx.y;
    const int tile0 = blockIdx.x * TILE_M;
    const int cnt = g_counts[s];
    if (tile0 >= cnt) return;

    extern __shared__ char smem[];
    const uint32_t smb = smem_u32(smem);
    const int tid = threadIdx.x;
    int* s_idx = (int*)(smem + SIDX);

    if (tid < TILE_M)
        s_idx[tid] = (tile0 + tid < cnt) ? g_lists[s * NATOMS + tile0 + tid] : -1;
    __syncthreads();

    /* gather + split layer-1 input: 32 rows x 384 f32 -> R0 hi/lo */
    for (int it = tid; it < TILE_M * 96; it += NTHREADS) {
        int r = it / 96, q = it - r * 96;
        int g = s_idx[r];
        float4 v = make_float4(0.f, 0.f, 0.f, 0.f);
        if (g >= 0) v = *(const float4*)(aev + (size_t)g * FDIM + q * 4);
        uint32_t h0, l0, h1, l1;
        split2(v.x, v.y, h0, l0);
        split2(v.z, v.w, h1, l1);
        uint32_t o = swoff((uint32_t)r, (uint32_t)(q * 8), 768);
        *(uint2*)(smem + R0_HI + o) = make_uint2(h0, h1);
        *(uint2*)(smem + R0_LO + o) = make_uint2(l0, l1);
    }
    __syncthreads();

    mlp_layer<K1, N1, 768, 512>(smem, smb, R0_HI, R0_LO, R1_HI, R1_LO,
        g_wh + W_OFF1 + (size_t)s * N1 * K1, g_wl + W_OFF1 + (size_t)s * N1 * K1,
        b1 + s * N1);
    mlp_layer<K2, N2, 512, 384>(smem, smb, R1_HI, R1_LO, R0_HI, R0_LO,
        g_wh + W_OFF2 + (size_t)s * N2 * K2, g_wl + W_OFF2 + (size_t)s * N2 * K2,
        b2 + s * N2);
    mlp_layer<K3, N3, 384, 384>(smem, smb, R0_HI, R0_LO, R1_HI, R1_LO,
        g_wh + W_OFF3 + (size_t)s * N3 * K3, g_wl + W_OFF3 + (size_t)s * N3 * K3,
        b3 + s * N3);

    /* layer 4: 160 -> 1 dot product */
    {
        const int wid = tid >> 5, lane = tid & 31;
        const float* w4s = W4 + s * N3;
        const float  b4v = __ldg(b4 + s);
#pragma unroll
        for (int rr = 0; rr < 4; rr++) {
            int row = wid * 4 + rr;
            float sum = 0.f;
#pragma unroll
            for (int c = lane; c < N3; c += 32) {
                uint32_t o = swoff((uint32_t)row, (uint32_t)(2 * c), 384);
                float hi = __bfloat162float(*(const __nv_bfloat16*)(smem + R1_HI + o));
                float lo = __bfloat162float(*(const __nv_bfloat16*)(smem + R1_LO + o));
                sum += (hi + lo) * __ldg(w4s + c);
            }
#pragma unroll
            for (int o = 16; o > 0; o >>= 1)
                sum += __shfl_down_sync(0xffffffffu, sum, o);
            if (lane == 0) {
                int g = s_idx[row];
                if (g >= 0) g_atom_energy[g] = sum + b4v;
            }
        }
    }
}

/* ---------------- per-molecule reduction -------------------------------- */
__global__ void reduce_kernel(float* __restrict__ out) {
    __shared__ float sh[64];
    const int b = blockIdx.x, t = threadIdx.x;
    sh[t] = (t < NA) ? g_atom_energy[b * NA + t] : 0.f;
    __syncthreads();
#pragma unroll
    for (int o = 32; o > 0; o >>= 1) {
        if (t < o) sh[t] += sh[t + o];
        __syncthreads();
    }
    if (t == 0) out[b] = sh[0];
}

/* ---------------- launch ------------------------------------------------ */
extern "C" void kernel_launch(void* const* d_in, const int* in_sizes, int n_in,
                              void* d_out, int out_size)
{
    const int*   species = (const int*)  d_in[0];
    const float* aev     = (const float*)d_in[1];
    const float* W1      = (const float*)d_in[2];
    const float* b1      = (const float*)d_in[3];
    const float* W2      = (const float*)d_in[4];
    const float* b2      = (const float*)d_in[5];
    const float* W3      = (const float*)d_in[6];
    const float* b3      = (const float*)d_in[7];
    const float* W4      = (const float*)d_in[8];
    const float* b4      = (const float*)d_in[9];
    float* out = (float*)d_out;

    cudaFuncSetAttribute(mlp_kernel, cudaFuncAttributeMaxDynamicSharedMemorySize, SMEM_TOTAL);

    prep_split_kernel<<<(W_TOTAL + 255) / 256, 256>>>(W1, W2, W3);
    zero_kernel<<<1, 32>>>();
    bucket_kernel<<<(NATOMS + 255) / 256, 256>>>(species);

    dim3 grid(NATOMS / TILE_M, NUM_SPECIES);
    mlp_kernel<<<grid, NTHREADS, SMEM_TOTAL>>>(aev, b1, b2, b3, W4, b4);

    reduce_kernel<<<BMOL, 64>>>(out);
}

// round 6
// speedup vs baseline: 1.1652x; 1.1652x over previous
#include <cuda_runtime.h>
#include <cuda_bf16.h>
#include <cstdint>

#define NUM_SPECIES 7
#define BMOL 1024
#define NA 48
#define NATOMS (BMOL * NA)   /* 49152 */
#define FDIM 384
#define TILE_M 64
#define NTHREADS 512

/* layer sizes */
#define N1 256
#define N2 192
#define N3 160
#define K1 384
#define K2 256
#define K3 192

#define W1_ELEMS (NUM_SPECIES * N1 * K1)
#define W2_ELEMS (NUM_SPECIES * N2 * K2)
#define W3_ELEMS (NUM_SPECIES * N3 * K3)
#define W_OFF1 0
#define W_OFF2 (W1_ELEMS)
#define W_OFF3 (W1_ELEMS + W2_ELEMS)
#define W_TOTAL (W1_ELEMS + W2_ELEMS + W3_ELEMS)

__device__ int   g_counts[NUM_SPECIES];
__device__ int   g_lists[NUM_SPECIES * NATOMS];
__device__ float g_atom_energy[NATOMS];
__device__ __align__(16) __nv_bfloat16 g_wh[W_TOTAL];
__device__ __align__(16) __nv_bfloat16 g_wl[W_TOTAL];

/* ---------------- SMEM byte offsets ------------------------------------- */
#define R0_HI 0          /* 64 x 768B */
#define R0_LO 49152
#define R1_HI 98304      /* 64 x 512B */
#define R1_LO 131072
#define WBUF  163840     /* 2 x 32KB; row = [hi 64B | lo 64B], XOR swizzle */
#define SIDX  229376     /* 64 x int */
#define SMEM_TOTAL 229632

/* ---------------- PTX helpers ------------------------------------------- */
__device__ __forceinline__ uint32_t smem_u32(const void* p) {
    uint32_t a;
    asm("{ .reg .u64 t; cvta.to.shared.u64 t, %1; cvt.u32.u64 %0, t; }" : "=r"(a) : "l"(p));
    return a;
}
__device__ __forceinline__ void cp16(uint32_t dst, const void* src) {
    asm volatile("cp.async.ca.shared.global [%0], [%1], 16;" :: "r"(dst), "l"(src));
}
#define CP_COMMIT() asm volatile("cp.async.commit_group;" ::: "memory")
#define CP_WAIT1()  asm volatile("cp.async.wait_group 1;" ::: "memory")

__device__ __forceinline__ void ldsm4(uint32_t (&r)[4], uint32_t a) {
    asm volatile("ldmatrix.sync.aligned.m8n8.x4.shared.b16 {%0,%1,%2,%3}, [%4];"
        : "=r"(r[0]), "=r"(r[1]), "=r"(r[2]), "=r"(r[3]) : "r"(a));
}
__device__ __forceinline__ void mma16816(float (&c)[4], const uint32_t (&a)[4],
                                         uint32_t b0, uint32_t b1) {
    asm volatile("mma.sync.aligned.m16n8k16.row.col.f32.bf16.bf16.f32 "
        "{%0,%1,%2,%3},{%4,%5,%6,%7},{%8,%9},{%0,%1,%2,%3};"
        : "+f"(c[0]), "+f"(c[1]), "+f"(c[2]), "+f"(c[3])
        : "r"(a[0]), "r"(a[1]), "r"(a[2]), "r"(a[3]), "r"(b0), "r"(b1));
}

/* swizzled byte offset of (row r, byte-in-row kb); rowb multiple of 128 */
__device__ __forceinline__ uint32_t swoff(uint32_t r, uint32_t kb, uint32_t rowb) {
    return r * rowb + (kb & ~127u) + ((((kb >> 4) ^ r) & 7u) << 4) + (kb & 15u);
}

__device__ __forceinline__ void split2(float a, float b, uint32_t& hp, uint32_t& lp) {
    __nv_bfloat16 ha = __float2bfloat16(a), hb = __float2bfloat16(b);
    __nv_bfloat16 la = __float2bfloat16(a - __bfloat162float(ha));
    __nv_bfloat16 lb = __float2bfloat16(b - __bfloat162float(hb));
    hp = ((uint32_t)__bfloat16_as_ushort(hb) << 16) | __bfloat16_as_ushort(ha);
    lp = ((uint32_t)__bfloat16_as_ushort(lb) << 16) | __bfloat16_as_ushort(la);
}
__device__ __forceinline__ float celu01(float x) {
    return x > 0.f ? x : 0.1f * (__expf(10.f * x) - 1.f);
}

/* ---------------- prep / bucket ----------------------------------------- */
__global__ void prep_split_kernel(const float* __restrict__ W1,
                                  const float* __restrict__ W2,
                                  const float* __restrict__ W3) {
    int i = blockIdx.x * blockDim.x + threadIdx.x;
    if (i >= W_TOTAL) return;
    float v;
    if (i < W_OFF2)      v = W1[i - W_OFF1];
    else if (i < W_OFF3) v = W2[i - W_OFF2];
    else                 v = W3[i - W_OFF3];
    __nv_bfloat16 h = __float2bfloat16(v);
    g_wh[i] = h;
    g_wl[i] = __float2bfloat16(v - __bfloat162float(h));
}
__global__ void zero_kernel() { if (threadIdx.x < NUM_SPECIES) g_counts[threadIdx.x] = 0; }
__global__ void bucket_kernel(const int* __restrict__ species) {
    int i = blockIdx.x * blockDim.x + threadIdx.x;
    if (i < NATOMS) {
        int s = species[i];
        g_lists[s * NATOMS + atomicAdd(&g_counts[s], 1)] = i;
    }
}

/* ---------------- one MLP layer on tensor cores ------------------------- */
/* out[64, N] = celu(in[64, K] * W[N, K]^T + bias)                          */
/* warp grid 2(M: 32 rows) x 8(N: 32 cols); full-N register accumulation.   */
/* W staged in 32-k chunks for ALL N rows: row = [hi 64B | lo 64B] swizzled */
template<int K, int N, int RIN, int ROUT>
__device__ __forceinline__ void mlp_layer(
    char* smem, uint32_t smb,
    uint32_t IN_HI, uint32_t IN_LO, uint32_t OUT_HI, uint32_t OUT_LO,
    const __nv_bfloat16* __restrict__ Wh, const __nv_bfloat16* __restrict__ Wl,
    const float* __restrict__ bias)
{
    const int tid = threadIdx.x;
    const int lane = tid & 31, wid = tid >> 5;
    const int wm = wid & 1, wn = wid >> 1;          /* 2 x 8 warps */
    constexpr int NK = K / 32;
    const bool active = (wn * 32) < N;

    const uint32_t lrow = (uint32_t)((lane & 7) + (lane & 8)); /* 0..15 */
    const uint32_t lk   = (uint32_t)(lane >> 4);               /* 0 / 1  */

    /* stage weight chunk kcc (32 k, all N rows) into buffer buf */
    auto stage = [&](int kcc, int buf) {
        uint32_t wb = smb + WBUF + (uint32_t)buf * 32768u;
        for (int it = tid; it < N * 8; it += NTHREADS) {
            int rr = it >> 3, cc = it & 7;
            const __nv_bfloat16* src = (cc < 4)
                ? Wh + (size_t)rr * K + kcc * 32 + cc * 8
                : Wl + (size_t)rr * K + kcc * 32 + (cc - 4) * 8;
            cp16(wb + (uint32_t)(rr * 128 + ((cc ^ (rr & 7)) << 4)), src);
        }
    };

    stage(0, 0); CP_COMMIT();
    stage(1, 1); CP_COMMIT();

    float acc[2][4][4];   /* [mt][nt][frag] : rows wm*32+mt*16, cols wn*32+nt*8 */
#pragma unroll
    for (int a = 0; a < 2; a++)
#pragma unroll
        for (int b = 0; b < 4; b++)
#pragma unroll
            for (int c = 0; c < 4; c++) acc[a][b][c] = 0.f;

    for (int kc = 0; kc < NK; kc++) {
        CP_WAIT1();
        __syncthreads();
        const uint32_t wb = smb + WBUF + (uint32_t)(kc & 1) * 32768u;
        if (active) {
#pragma unroll
            for (int s = 0; s < 2; s++) {          /* two k16 steps per chunk */
                uint32_t ah[2][4], al[2][4], wh[2][4], wl[2][4];
                /* A fragments: 32 rows hi/lo */
#pragma unroll
                for (int mt = 0; mt < 2; mt++) {
                    uint32_t r = (uint32_t)(wm * 32 + mt * 16) + lrow;
                    uint32_t kb = (uint32_t)(kc * 64 + s * 32) + lk * 16u;
                    uint32_t a = swoff(r, kb, RIN);
                    ldsm4(ah[mt], smb + IN_HI + a);
                    ldsm4(al[mt], smb + IN_LO + a);
                }
                /* W fragments: 32 n-rows hi/lo */
#pragma unroll
                for (int nh = 0; nh < 2; nh++) {
                    uint32_t r = (uint32_t)(wn * 32 + nh * 16) + lrow;
                    uint32_t ch = (uint32_t)(s * 2) + lk;
                    uint32_t oh = r * 128 + ((ch ^ (r & 7u)) << 4);
                    uint32_t ol = r * 128 + (((ch + 4) ^ (r & 7u)) << 4);
                    ldsm4(wh[nh], wb + oh);
                    ldsm4(wl[nh], wb + ol);
                }
                /* 24 MMAs */
#pragma unroll
                for (int mt = 0; mt < 2; mt++)
#pragma unroll
                    for (int nh = 0; nh < 2; nh++)
#pragma unroll
                        for (int j = 0; j < 2; j++) {
                            float (&ac)[4] = acc[mt][nh * 2 + j];
                            mma16816(ac, ah[mt], wh[nh][j], wh[nh][j + 2]);
                            mma16816(ac, ah[mt], wl[nh][j], wl[nh][j + 2]);
                            mma16816(ac, al[mt], wh[nh][j], wh[nh][j + 2]);
                        }
            }
        }
        __syncthreads();
        if (kc + 2 < NK) { stage(kc + 2, kc & 1); }
        CP_COMMIT();
    }

    /* epilogue: bias + celu + split -> OUT region */
    if (active) {
#pragma unroll
        for (int mt = 0; mt < 2; mt++)
#pragma unroll
            for (int nt = 0; nt < 4; nt++) {
                uint32_t r0 = (uint32_t)(wm * 32 + mt * 16 + (lane >> 2));
                int c = wn * 32 + nt * 8 + 2 * (lane & 3);
                float b0 = __ldg(bias + c), b1 = __ldg(bias + c + 1);
                float v00 = celu01(acc[mt][nt][0] + b0);
                float v01 = celu01(acc[mt][nt][1] + b1);
                float v10 = celu01(acc[mt][nt][2] + b0);
                float v11 = celu01(acc[mt][nt][3] + b1);
                uint32_t hp, lp;
                uint32_t o0 = swoff(r0, (uint32_t)(2 * c), ROUT);
                split2(v00, v01, hp, lp);
                *(uint32_t*)(smem + OUT_HI + o0) = hp;
                *(uint32_t*)(smem + OUT_LO + o0) = lp;
                uint32_t o1 = swoff(r0 + 8, (uint32_t)(2 * c), ROUT);
                split2(v10, v11, hp, lp);
                *(uint32_t*)(smem + OUT_HI + o1) = hp;
                *(uint32_t*)(smem + OUT_LO + o1) = lp;
            }
    }
    __syncthreads();
}

/* ---------------- main kernel ------------------------------------------- */
__global__ void __launch_bounds__(NTHREADS, 1)
mlp_kernel(const float* __restrict__ aev,
           const float* __restrict__ b1, const float* __restrict__ b2,
           const float* __restrict__ b3,
           const float* __restrict__ W4, const float* __restrict__ b4)
{
    const int s = blockIdx.y;
    const int tile0 = blockIdx.x * TILE_M;
    const int cnt = g_counts[s];
    if (tile0 >= cnt) return;

    extern __shared__ char smem[];
    const uint32_t smb = smem_u32(smem);
    const int tid = threadIdx.x;
    int* s_idx = (int*)(smem + SIDX);

    if (tid < TILE_M)
        s_idx[tid] = (tile0 + tid < cnt) ? g_lists[s * NATOMS + tile0 + tid] : -1;
    __syncthreads();

    /* gather + split layer-1 input: 64 rows x 384 f32 -> R0 hi/lo */
    for (int it = tid; it < TILE_M * 96; it += NTHREADS) {
        int r = it / 96, q = it - r * 96;
        int g = s_idx[r];
        float4 v = make_float4(0.f, 0.f, 0.f, 0.f);
        if (g >= 0) v = *(const float4*)(aev + (size_t)g * FDIM + q * 4);
        uint32_t h0, l0, h1, l1;
        split2(v.x, v.y, h0, l0);
        split2(v.z, v.w, h1, l1);
        uint32_t o = swoff((uint32_t)r, (uint32_t)(q * 8), 768);
        *(uint2*)(smem + R0_HI + o) = make_uint2(h0, h1);
        *(uint2*)(smem + R0_LO + o) = make_uint2(l0, l1);
    }
    __syncthreads();

    mlp_layer<K1, N1, 768, 512>(smem, smb, R0_HI, R0_LO, R1_HI, R1_LO,
        g_wh + W_OFF1 + (size_t)s * N1 * K1, g_wl + W_OFF1 + (size_t)s * N1 * K1,
        b1 + s * N1);
    mlp_layer<K2, N2, 512, 384>(smem, smb, R1_HI, R1_LO, R0_HI, R0_LO,
        g_wh + W_OFF2 + (size_t)s * N2 * K2, g_wl + W_OFF2 + (size_t)s * N2 * K2,
        b2 + s * N2);
    mlp_layer<K3, N3, 384, 384>(smem, smb, R0_HI, R0_LO, R1_HI, R1_LO,
        g_wh + W_OFF3 + (size_t)s * N3 * K3, g_wl + W_OFF3 + (size_t)s * N3 * K3,
        b3 + s * N3);

    /* layer 4: 160 -> 1 dot product */
    {
        const int wid = tid >> 5, lane = tid & 31;
        const float* w4s = W4 + s * N3;
        const float  b4v = __ldg(b4 + s);
#pragma unroll
        for (int rr = 0; rr < 4; rr++) {
            int row = wid * 4 + rr;
            float sum = 0.f;
#pragma unroll
            for (int c = lane; c < N3; c += 32) {
                uint32_t o = swoff((uint32_t)row, (uint32_t)(2 * c), 384);
                float hi = __bfloat162float(*(const __nv_bfloat16*)(smem + R1_HI + o));
                float lo = __bfloat162float(*(const __nv_bfloat16*)(smem + R1_LO + o));
                sum += (hi + lo) * __ldg(w4s + c);
            }
#pragma unroll
            for (int o = 16; o > 0; o >>= 1)
                sum += __shfl_down_sync(0xffffffffu, sum, o);
            if (lane == 0) {
                int g = s_idx[row];
                if (g >= 0) g_atom_energy[g] = sum + b4v;
            }
        }
    }
}

/* ---------------- per-molecule reduction -------------------------------- */
__global__ void reduce_kernel(float* __restrict__ out) {
    __shared__ float sh[64];
    const int b = blockIdx.x, t = threadIdx.x;
    sh[t] = (t < NA) ? g_atom_energy[b * NA + t] : 0.f;
    __syncthreads();
#pragma unroll
    for (int o = 32; o > 0; o >>= 1) {
        if (t < o) sh[t] += sh[t + o];
        __syncthreads();
    }
    if (t == 0) out[b] = sh[0];
}

/* ---------------- launch ------------------------------------------------ */
extern "C" void kernel_launch(void* const* d_in, const int* in_sizes, int n_in,
                              void* d_out, int out_size)
{
    const int*   species = (const int*)  d_in[0];
    const float* aev     = (const float*)d_in[1];
    const float* W1      = (const float*)d_in[2];
    const float* b1      = (const float*)d_in[3];
    const float* W2      = (const float*)d_in[4];
    const float* b2      = (const float*)d_in[5];
    const float* W3      = (const float*)d_in[6];
    const float* b3      = (const float*)d_in[7];
    const float* W4      = (const float*)d_in[8];
    const float* b4      = (const float*)d_in[9];
    float* out = (float*)d_out;

    cudaFuncSetAttribute(mlp_kernel, cudaFuncAttributeMaxDynamicSharedMemorySize, SMEM_TOTAL);

    prep_split_kernel<<<(W_TOTAL + 255) / 256, 256>>>(W1, W2, W3);
    zero_kernel<<<1, 32>>>();
    bucket_kernel<<<(NATOMS + 255) / 256, 256>>>(species);

    dim3 grid(NATOMS / TILE_M, NUM_SPECIES);
    mlp_kernel<<<grid, NTHREADS, SMEM_TOTAL>>>(aev, b1, b2, b3, W4, b4);

    reduce_kernel<<<BMOL, 64>>>(out);
}

// round 7
// speedup vs baseline: 2.5381x; 2.1783x over previous
#include <cuda_runtime.h>
#include <cuda_fp16.h>
#include <cstdint>

#define NUM_SPECIES 7
#define BMOL 1024
#define NA 48
#define NATOMS (BMOL * NA)   /* 49152 */
#define FDIM 384
#define TILE_M 128
#define NTHREADS 512

/* layer sizes */
#define N1 256
#define N2 192
#define N3 160
#define K1 384
#define K2 256
#define K3 192

#define W1_ELEMS (NUM_SPECIES * N1 * K1)
#define W2_ELEMS (NUM_SPECIES * N2 * K2)
#define W3_ELEMS (NUM_SPECIES * N3 * K3)
#define W_OFF1 0
#define W_OFF2 (W1_ELEMS)
#define W_OFF3 (W1_ELEMS + W2_ELEMS)
#define W_TOTAL (W1_ELEMS + W2_ELEMS + W3_ELEMS)

__device__ int   g_counts[NUM_SPECIES];
__device__ int   g_lists[NUM_SPECIES * NATOMS];
__device__ float g_atom_energy[NATOMS];
__device__ __align__(16) __half g_w[W_TOTAL];

/* ---------------- SMEM byte offsets (total 229888 <= 232448) ------------- */
#define R0_OFF 0         /* 128 rows x 768B (384 fp16)  = 98304 */
#define R1_OFF 98304     /* 128 rows x 512B (256 fp16)  = 65536 */
#define WBUF   163840    /* 2 x 32KB; row = 128B (64 k fp16), XOR swizzle */
#define SIDX   229376    /* 128 x int */
#define SMEM_TOTAL 229888

/* ---------------- PTX helpers ------------------------------------------- */
__device__ __forceinline__ uint32_t smem_u32(const void* p) {
    uint32_t a;
    asm("{ .reg .u64 t; cvta.to.shared.u64 t, %1; cvt.u32.u64 %0, t; }" : "=r"(a) : "l"(p));
    return a;
}
__device__ __forceinline__ void cp16(uint32_t dst, const void* src) {
    asm volatile("cp.async.ca.shared.global [%0], [%1], 16;" :: "r"(dst), "l"(src));
}
#define CP_COMMIT() asm volatile("cp.async.commit_group;" ::: "memory")
#define CP_WAIT1()  asm volatile("cp.async.wait_group 1;" ::: "memory")

__device__ __forceinline__ void ldsm4(uint32_t (&r)[4], uint32_t a) {
    asm volatile("ldmatrix.sync.aligned.m8n8.x4.shared.b16 {%0,%1,%2,%3}, [%4];"
        : "=r"(r[0]), "=r"(r[1]), "=r"(r[2]), "=r"(r[3]) : "r"(a));
}
__device__ __forceinline__ void mma16816(float (&c)[4], const uint32_t (&a)[4],
                                         uint32_t b0, uint32_t b1) {
    asm volatile("mma.sync.aligned.m16n8k16.row.col.f32.f16.f16.f32 "
        "{%0,%1,%2,%3},{%4,%5,%6,%7},{%8,%9},{%0,%1,%2,%3};"
        : "+f"(c[0]), "+f"(c[1]), "+f"(c[2]), "+f"(c[3])
        : "r"(a[0]), "r"(a[1]), "r"(a[2]), "r"(a[3]), "r"(b0), "r"(b1));
}

/* swizzled byte offset of (row r, byte-in-row kb); rowb multiple of 128 */
__device__ __forceinline__ uint32_t swoff(uint32_t r, uint32_t kb, uint32_t rowb) {
    return r * rowb + (kb & ~127u) + ((((kb >> 4) ^ r) & 7u) << 4) + (kb & 15u);
}
__device__ __forceinline__ float celu01(float x) {
    return x > 0.f ? x : 0.1f * (__expf(10.f * x) - 1.f);
}

/* ---------------- prep / bucket ----------------------------------------- */
__global__ void prep_kernel(const float* __restrict__ W1,
                            const float* __restrict__ W2,
                            const float* __restrict__ W3) {
    int i = blockIdx.x * blockDim.x + threadIdx.x;
    if (i >= W_TOTAL) return;
    float v;
    if (i < W_OFF2)      v = W1[i - W_OFF1];
    else if (i < W_OFF3) v = W2[i - W_OFF2];
    else                 v = W3[i - W_OFF3];
    g_w[i] = __float2half_rn(v);
}
__global__ void zero_kernel() { if (threadIdx.x < NUM_SPECIES) g_counts[threadIdx.x] = 0; }
__global__ void bucket_kernel(const int* __restrict__ species) {
    int i = blockIdx.x * blockDim.x + threadIdx.x;
    if (i < NATOMS) {
        int s = species[i];
        g_lists[s * NATOMS + atomicAdd(&g_counts[s], 1)] = i;
    }
}

/* ---------------- one MLP layer on tensor cores (plain fp16) ------------ */
/* out[128, N] = celu(in[128, K] * W[N, K]^T + bias)                        */
/* 16 warps = 2(M: 64 rows) x 8(N); N split into n16 chunks round-robin.    */
/* W staged per 64-k chunk for ALL N rows: 128B/row, 8x16B XOR swizzle.     */
template<int K, int N, int RIN, int ROUT, bool LAST_CELU>
__device__ __forceinline__ void mlp_layer(
    char* smem, uint32_t smb, uint32_t IN_OFF, uint32_t OUT_OFF,
    const __half* __restrict__ Wf, const float* __restrict__ bias)
{
    const int tid = threadIdx.x;
    const int lane = tid & 31, wid = tid >> 5;
    const int wm = wid & 1, wn = wid >> 1;          /* 2 x 8 warps */
    constexpr int NKC = K / 64;                     /* 64-k chunks */
    constexpr int NCH = N / 16;                     /* n16 chunks  */

    const uint32_t lrow = (uint32_t)((lane & 7) + (lane & 8)); /* 0..15 */
    const uint32_t lk   = (uint32_t)(lane >> 4);               /* 0 / 1  */

    const int ch0 = wn, ch1 = wn + 8;
    const int nown = (ch1 < NCH) ? 2 : 1;

    /* staging: thread's row/slot invariant under rr += 64 */
    const int srr = tid >> 3, scc = tid & 7;
    const uint32_t sdst = (uint32_t)(srr * 128 + ((scc ^ (srr & 7)) << 4));

    auto stage = [&](int kcc, int buf) {
        uint32_t wb = smb + WBUF + (uint32_t)buf * 32768u + sdst;
        const __half* src = Wf + (size_t)srr * K + kcc * 64 + scc * 8;
#pragma unroll
        for (int i = 0; i < (N + 63) / 64; i++)
            if (srr + i * 64 < N)
                cp16(wb + (uint32_t)i * 8192u, src + (size_t)i * 64 * K);
    };

    stage(0, 0); CP_COMMIT();
    stage(1, 1); CP_COMMIT();

    float acc[2][4][2][4];   /* [chunk][mt][nt][frag] */
#pragma unroll
    for (int a = 0; a < 2; a++)
#pragma unroll
        for (int b = 0; b < 4; b++)
#pragma unroll
            for (int c = 0; c < 2; c++)
#pragma unroll
                for (int d = 0; d < 4; d++) acc[a][b][c][d] = 0.f;

    for (int kc = 0; kc < NKC; kc++) {
        CP_WAIT1();
        __syncthreads();
        const uint32_t wb = smb + WBUF + (uint32_t)(kc & 1) * 32768u;
#pragma unroll
        for (int s = 0; s < 4; s++) {               /* four k16 steps / chunk */
            uint32_t af[4][4];
#pragma unroll
            for (int mt = 0; mt < 4; mt++) {
                uint32_t r = (uint32_t)(wm * 64 + mt * 16) + lrow;
                uint32_t kb = (uint32_t)(kc * 128 + s * 32) + lk * 16u;
                ldsm4(af[mt], smb + IN_OFF + swoff(r, kb, RIN));
            }
            uint32_t wf[2][4];
#pragma unroll
            for (int ci = 0; ci < 2; ci++) {
                if (ci < nown) {
                    uint32_t r = (uint32_t)((ci ? ch1 : ch0) * 16) + lrow;
                    uint32_t slot = (uint32_t)(s * 2) + lk;
                    ldsm4(wf[ci], wb + r * 128 + ((slot ^ (r & 7u)) << 4));
                }
            }
#pragma unroll
            for (int ci = 0; ci < 2; ci++)
                if (ci < nown)
#pragma unroll
                    for (int mt = 0; mt < 4; mt++) {
                        mma16816(acc[ci][mt][0], af[mt], wf[ci][0], wf[ci][2]);
                        mma16816(acc[ci][mt][1], af[mt], wf[ci][1], wf[ci][3]);
                    }
        }
        __syncthreads();
        if (kc + 2 < NKC) stage(kc + 2, kc & 1);
        CP_COMMIT();
    }

    /* epilogue: bias + celu -> fp16 OUT */
#pragma unroll
    for (int ci = 0; ci < 2; ci++) {
        if (ci >= nown) break;
        const int cbase = (ci ? ch1 : ch0) * 16;
#pragma unroll
        for (int mt = 0; mt < 4; mt++)
#pragma unroll
            for (int nt = 0; nt < 2; nt++) {
                uint32_t r0 = (uint32_t)(wm * 64 + mt * 16 + (lane >> 2));
                int c = cbase + nt * 8 + 2 * (lane & 3);
                float b0 = __ldg(bias + c), b1 = __ldg(bias + c + 1);
                float v0 = acc[ci][mt][nt][0] + b0, v1 = acc[ci][mt][nt][1] + b1;
                float v2 = acc[ci][mt][nt][2] + b0, v3 = acc[ci][mt][nt][3] + b1;
                if (LAST_CELU) {
                    v0 = celu01(v0); v1 = celu01(v1);
                    v2 = celu01(v2); v3 = celu01(v3);
                }
                __half2 h01 = __floats2half2_rn(v0, v1);
                __half2 h23 = __floats2half2_rn(v2, v3);
                *(__half2*)(smem + OUT_OFF + swoff(r0,     (uint32_t)(2 * c), ROUT)) = h01;
                *(__half2*)(smem + OUT_OFF + swoff(r0 + 8, (uint32_t)(2 * c), ROUT)) = h23;
            }
    }
    __syncthreads();
}

/* ---------------- main kernel ------------------------------------------- */
__global__ void __launch_bounds__(NTHREADS, 1)
mlp_kernel(const float* __restrict__ aev,
           const float* __restrict__ b1, const float* __restrict__ b2,
           const float* __restrict__ b3,
           const float* __restrict__ W4, const float* __restrict__ b4)
{
    const int s = blockIdx.y;
    const int tile0 = blockIdx.x * TILE_M;
    const int cnt = g_counts[s];
    if (tile0 >= cnt) return;

    extern __shared__ char smem[];
    const uint32_t smb = smem_u32(smem);
    const int tid = threadIdx.x;
    int* s_idx = (int*)(smem + SIDX);

    if (tid < TILE_M)
        s_idx[tid] = (tile0 + tid < cnt) ? g_lists[s * NATOMS + tile0 + tid] : -1;
    __syncthreads();

    /* gather layer-1 input: 128 rows x 384 f32 -> R0 fp16 */
    for (int it = tid; it < TILE_M * 96; it += NTHREADS) {
        int r = it / 96, q = it - r * 96;
        int g = s_idx[r];
        float4 v = make_float4(0.f, 0.f, 0.f, 0.f);
        if (g >= 0) v = *(const float4*)(aev + (size_t)g * FDIM + q * 4);
        __half2 h01 = __floats2half2_rn(v.x, v.y);
        __half2 h23 = __floats2half2_rn(v.z, v.w);
        uint32_t o = swoff((uint32_t)r, (uint32_t)(q * 8), 768);
        *(uint2*)(smem + R0_OFF + o) =
            make_uint2(*(uint32_t*)&h01, *(uint32_t*)&h23);
    }
    __syncthreads();

    /* L1: R0(768) -> R1(512); L2: R1(512) -> R0(384); L3: R0(384) -> R1(384) */
    mlp_layer<K1, N1, 768, 512, true>(smem, smb, R0_OFF, R1_OFF,
        g_w + W_OFF1 + (size_t)s * N1 * K1, b1 + s * N1);
    mlp_layer<K2, N2, 512, 384, true>(smem, smb, R1_OFF, R0_OFF,
        g_w + W_OFF2 + (size_t)s * N2 * K2, b2 + s * N2);
    mlp_layer<K3, N3, 384, 384, true>(smem, smb, R0_OFF, R1_OFF,
        g_w + W_OFF3 + (size_t)s * N3 * K3, b3 + s * N3);

    /* layer 4: 160 -> 1 dot product */
    {
        const int wid = tid >> 5, lane = tid & 31;
        const float* w4s = W4 + s * N3;
        const float  b4v = __ldg(b4 + s);
#pragma unroll
        for (int rr = 0; rr < 8; rr++) {
            int row = wid * 8 + rr;
            float sum = 0.f;
#pragma unroll
            for (int c = lane; c < N3; c += 32) {
                uint32_t o = swoff((uint32_t)row, (uint32_t)(2 * c), 384);
                sum += __half2float(*(const __half*)(smem + R1_OFF + o)) * __ldg(w4s + c);
            }
#pragma unroll
            for (int o = 16; o > 0; o >>= 1)
                sum += __shfl_down_sync(0xffffffffu, sum, o);
            if (lane == 0) {
                int g = s_idx[row];
                if (g >= 0) g_atom_energy[g] = sum + b4v;
            }
        }
    }
}

/* ---------------- per-molecule reduction -------------------------------- */
__global__ void reduce_kernel(float* __restrict__ out) {
    __shared__ float sh[64];
    const int b = blockIdx.x, t = threadIdx.x;
    sh[t] = (t < NA) ? g_atom_energy[b * NA + t] : 0.f;
    __syncthreads();
#pragma unroll
    for (int o = 32; o > 0; o >>= 1) {
        if (t < o) sh[t] += sh[t + o];
        __syncthreads();
    }
    if (t == 0) out[b] = sh[0];
}

/* ---------------- launch ------------------------------------------------ */
extern "C" void kernel_launch(void* const* d_in, const int* in_sizes, int n_in,
                              void* d_out, int out_size)
{
    const int*   species = (const int*)  d_in[0];
    const float* aev     = (const float*)d_in[1];
    const float* W1      = (const float*)d_in[2];
    const float* b1      = (const float*)d_in[3];
    const float* W2      = (const float*)d_in[4];
    const float* b2      = (const float*)d_in[5];
    const float* W3      = (const float*)d_in[6];
    const float* b3      = (const float*)d_in[7];
    const float* W4      = (const float*)d_in[8];
    const float* b4      = (const float*)d_in[9];
    float* out = (float*)d_out;

    cudaFuncSetAttribute(mlp_kernel, cudaFuncAttributeMaxDynamicSharedMemorySize, SMEM_TOTAL);

    prep_kernel<<<(W_TOTAL + 255) / 256, 256>>>(W1, W2, W3);
    zero_kernel<<<1, 32>>>();
    bucket_kernel<<<(NATOMS + 255) / 256, 256>>>(species);

    dim3 grid(NATOMS / TILE_M, NUM_SPECIES);
    mlp_kernel<<<grid, NTHREADS, SMEM_TOTAL>>>(aev, b1, b2, b3, W4, b4);

    reduce_kernel<<<BMOL, 64>>>(out);
}

// round 9
// speedup vs baseline: 2.6924x; 1.0608x over previous
#include <cuda_runtime.h>
#include <cuda_fp16.h>
#include <cstdint>

#define NUM_SPECIES 7
#define BMOL 1024
#define NA 48
#define NATOMS (BMOL * NA)   /* 49152 */
#define FDIM 384
#define TILE_M 128
#define NTHREADS 512

/* layer sizes */
#define N1 256
#define N2 192
#define N3 160
#define K1 384
#define K2 256
#define K3 192

#define W1_ELEMS (NUM_SPECIES * N1 * K1)
#define W2_ELEMS (NUM_SPECIES * N2 * K2)
#define W3_ELEMS (NUM_SPECIES * N3 * K3)
#define W_OFF1 0
#define W_OFF2 (W1_ELEMS)
#define W_OFF3 (W1_ELEMS + W2_ELEMS)
#define W_TOTAL (W1_ELEMS + W2_ELEMS + W3_ELEMS)

__device__ int   g_counts[NUM_SPECIES];
__device__ int   g_lists[NUM_SPECIES * NATOMS];
__device__ float g_atom_energy[NATOMS];
__device__ __align__(16) __half g_w[W_TOTAL];

/* ---------------- SMEM byte offsets (total 229888) ----------------------- */
#define R0_OFF 0         /* 128 rows x 768B (384 fp16) = 98304 */
#define R1_OFF 98304     /* 128 rows x 512B (256 fp16) = 65536; PACC aliases */
#define PACC   R1_OFF    /* 128 rows x 8 warp-partials f32 = 4096 (L3 only) */
#define WBUF   163840    /* 2 x 32KB; row = 128B (64 k fp16), XOR swizzle */
#define SIDX   229376    /* 128 x int */
#define SMEM_TOTAL 229888

/* ---------------- PTX helpers ------------------------------------------- */
__device__ __forceinline__ uint32_t smem_u32(const void* p) {
    uint32_t a;
    asm("{ .reg .u64 t; cvta.to.shared.u64 t, %1; cvt.u32.u64 %0, t; }" : "=r"(a) : "l"(p));
    return a;
}
__device__ __forceinline__ void cp16(uint32_t dst, const void* src) {
    asm volatile("cp.async.ca.shared.global [%0], [%1], 16;" :: "r"(dst), "l"(src));
}
#define CP_COMMIT() asm volatile("cp.async.commit_group;" ::: "memory")
#define CP_WAIT1()  asm volatile("cp.async.wait_group 1;" ::: "memory")
/* pairwise barrier: the 2 warps (wm=0/1) sharing wn sync on id wn+1 */
#define PAIR_BAR(wn) asm volatile("bar.sync %0, 64;" :: "r"((wn) + 1) : "memory")

__device__ __forceinline__ void ldsm4(uint32_t (&r)[4], uint32_t a) {
    asm volatile("ldmatrix.sync.aligned.m8n8.x4.shared.b16 {%0,%1,%2,%3}, [%4];"
        : "=r"(r[0]), "=r"(r[1]), "=r"(r[2]), "=r"(r[3]) : "r"(a));
}
__device__ __forceinline__ void mma16816(float (&c)[4], const uint32_t (&a)[4],
                                         uint32_t b0, uint32_t b1) {
    asm volatile("mma.sync.aligned.m16n8k16.row.col.f32.f16.f16.f32 "
        "{%0,%1,%2,%3},{%4,%5,%6,%7},{%8,%9},{%0,%1,%2,%3};"
        : "+f"(c[0]), "+f"(c[1]), "+f"(c[2]), "+f"(c[3])
        : "r"(a[0]), "r"(a[1]), "r"(a[2]), "r"(a[3]), "r"(b0), "r"(b1));
}

/* swizzled byte offset of (row r, byte-in-row kb); rowb multiple of 128 */
__device__ __forceinline__ uint32_t swoff(uint32_t r, uint32_t kb, uint32_t rowb) {
    return r * rowb + (kb & ~127u) + ((((kb >> 4) ^ r) & 7u) << 4) + (kb & 15u);
}
__device__ __forceinline__ float celu01(float x) {
    return x > 0.f ? x : 0.1f * (__expf(10.f * x) - 1.f);
}

/* ---------------- prep / bucket ----------------------------------------- */
__global__ void prep_kernel(const float* __restrict__ W1,
                            const float* __restrict__ W2,
                            const float* __restrict__ W3) {
    int i = blockIdx.x * blockDim.x + threadIdx.x;
    if (i >= W_TOTAL) return;
    float v;
    if (i < W_OFF2)      v = W1[i - W_OFF1];
    else if (i < W_OFF3) v = W2[i - W_OFF2];
    else                 v = W3[i - W_OFF3];
    g_w[i] = __float2half_rn(v);
}
__global__ void zero_kernel() { if (threadIdx.x < NUM_SPECIES) g_counts[threadIdx.x] = 0; }
__global__ void bucket_kernel(const int* __restrict__ species) {
    int i = blockIdx.x * blockDim.x + threadIdx.x;
    if (i < NATOMS) {
        int s = species[i];
        g_lists[s * NATOMS + atomicAdd(&g_counts[s], 1)] = i;
    }
}

/* ============ warp-private weight staging =============================== */
template<int K>
__device__ __forceinline__ void stage_w(
    uint32_t smb, const __half* __restrict__ Wf,
    int ch0, int ch1, int nown, int lane, int kcc, int buf)
{
    uint32_t wb = smb + WBUF + (uint32_t)buf * 32768u;
#pragma unroll
    for (int ci = 0; ci < 2; ci++) {
        if (ci >= nown) break;
        const int ch = ci ? ch1 : ch0;
#pragma unroll
        for (int i = 0; i < 4; i++) {
            int u = lane + 32 * i;              /* 0..127 */
            int row = ch * 16 + (u >> 3);
            int slot = u & 7;
            uint32_t d = wb + (uint32_t)(row * 128 + ((slot ^ (row & 7)) << 4));
            cp16(d, Wf + (size_t)row * K + kcc * 64 + slot * 8);
        }
    }
}

/* ---------------- one MLP layer (fp16 HMMA, pair-synced k-loop) --------- */
template<int K, int N, int RIN, int ROUT, bool FUSE>
__device__ __forceinline__ void mlp_layer(
    char* smem, uint32_t smb, uint32_t IN_OFF, uint32_t OUT_OFF,
    const __half* __restrict__ Wf, const float* __restrict__ bias,
    const float* __restrict__ w4 /* only for FUSE */)
{
    const int tid = threadIdx.x;
    const int lane = tid & 31, wid = tid >> 5;
    const int wm = wid & 1, wn = wid >> 1;          /* 2 x 8 warps */
    constexpr int NKC = K / 64;
    constexpr int NCH = N / 16;

    const uint32_t lrow = (uint32_t)((lane & 7) + (lane & 8)); /* 0..15 */
    const uint32_t lk   = (uint32_t)(lane >> 4);               /* 0 / 1  */
    const int ch0 = wn, ch1 = wn + 8;
    const int nown = (ch1 < NCH) ? 2 : 1;

    stage_w<K>(smb, Wf, ch0, ch1, nown, lane, 0, 0); CP_COMMIT();
    stage_w<K>(smb, Wf, ch0, ch1, nown, lane, 1, 1); CP_COMMIT();

    float acc[2][4][2][4];   /* [chunk][mt][nt][frag] */
#pragma unroll
    for (int a = 0; a < 2; a++)
#pragma unroll
        for (int b = 0; b < 4; b++)
#pragma unroll
            for (int c = 0; c < 2; c++)
#pragma unroll
                for (int d = 0; d < 4; d++) acc[a][b][c][d] = 0.f;

    for (int kc = 0; kc < NKC; kc++) {
        CP_WAIT1();
        __syncwarp();
        const uint32_t wb = smb + WBUF + (uint32_t)(kc & 1) * 32768u;
#pragma unroll
        for (int s = 0; s < 4; s++) {               /* four k16 steps */
            uint32_t af[4][4];
#pragma unroll
            for (int mt = 0; mt < 4; mt++) {
                uint32_t r = (uint32_t)(wm * 64 + mt * 16) + lrow;
                uint32_t kb = (uint32_t)(kc * 128 + s * 32) + lk * 16u;
                ldsm4(af[mt], smb + IN_OFF + swoff(r, kb, RIN));
            }
            uint32_t wf[2][4];
#pragma unroll
            for (int ci = 0; ci < 2; ci++) {
                if (ci >= nown) break;
                uint32_t r = (uint32_t)((ci ? ch1 : ch0) * 16) + lrow;
                uint32_t slot = (uint32_t)(s * 2) + lk;
                ldsm4(wf[ci], wb + r * 128 + ((slot ^ (r & 7u)) << 4));
            }
#pragma unroll
            for (int ci = 0; ci < 2; ci++) {
                if (ci >= nown) break;
#pragma unroll
                for (int mt = 0; mt < 4; mt++) {
                    mma16816(acc[ci][mt][0], af[mt], wf[ci][0], wf[ci][2]);
                    mma16816(acc[ci][mt][1], af[mt], wf[ci][1], wf[ci][3]);
                }
            }
        }
        /* pair barrier: partner warp done reading this buffer before restage */
        PAIR_BAR(wn);
        if (kc + 2 < NKC) stage_w<K>(smb, Wf, ch0, ch1, nown, lane, kc + 2, kc & 1);
        CP_COMMIT();
    }

    if (!FUSE) {
        /* epilogue: bias + celu -> fp16 OUT */
#pragma unroll
        for (int ci = 0; ci < 2; ci++) {
            if (ci >= nown) break;
            const int cbase = (ci ? ch1 : ch0) * 16;
#pragma unroll
            for (int mt = 0; mt < 4; mt++)
#pragma unroll
                for (int nt = 0; nt < 2; nt++) {
                    uint32_t r0 = (uint32_t)(wm * 64 + mt * 16 + (lane >> 2));
                    int c = cbase + nt * 8 + 2 * (lane & 3);
                    float b0 = __ldg(bias + c), b1 = __ldg(bias + c + 1);
                    float v0 = celu01(acc[ci][mt][nt][0] + b0);
                    float v1 = celu01(acc[ci][mt][nt][1] + b1);
                    float v2 = celu01(acc[ci][mt][nt][2] + b0);
                    float v3 = celu01(acc[ci][mt][nt][3] + b1);
                    __half2 h01 = __floats2half2_rn(v0, v1);
                    __half2 h23 = __floats2half2_rn(v2, v3);
                    *(__half2*)(smem + OUT_OFF + swoff(r0,     (uint32_t)(2 * c), ROUT)) = h01;
                    *(__half2*)(smem + OUT_OFF + swoff(r0 + 8, (uint32_t)(2 * c), ROUT)) = h23;
                }
        }
    } else {
        /* fused L3 epilogue + L4 dot: per-thread partials over owned cols */
        float* pacc = (float*)(smem + PACC);
#pragma unroll
        for (int mt = 0; mt < 4; mt++) {
            float p_lo = 0.f, p_hi = 0.f;
#pragma unroll
            for (int ci = 0; ci < 2; ci++) {
                if (ci >= nown) break;
                const int cbase = (ci ? ch1 : ch0) * 16;
#pragma unroll
                for (int nt = 0; nt < 2; nt++) {
                    int c = cbase + nt * 8 + 2 * (lane & 3);
                    float b0 = __ldg(bias + c), b1 = __ldg(bias + c + 1);
                    float w0 = __ldg(w4 + c),   w1 = __ldg(w4 + c + 1);
                    p_lo += celu01(acc[ci][mt][nt][0] + b0) * w0
                          + celu01(acc[ci][mt][nt][1] + b1) * w1;
                    p_hi += celu01(acc[ci][mt][nt][2] + b0) * w0
                          + celu01(acc[ci][mt][nt][3] + b1) * w1;
                }
            }
            /* deterministic quad reduction (lanes lane&3 share the row) */
            p_lo += __shfl_xor_sync(0xffffffffu, p_lo, 1);
            p_lo += __shfl_xor_sync(0xffffffffu, p_lo, 2);
            p_hi += __shfl_xor_sync(0xffffffffu, p_hi, 1);
            p_hi += __shfl_xor_sync(0xffffffffu, p_hi, 2);
            if ((lane & 3) == 0) {
                int r0 = wm * 64 + mt * 16 + (lane >> 2);
                pacc[r0 * 8 + wn] = p_lo;
                pacc[(r0 + 8) * 8 + wn] = p_hi;
            }
        }
    }
}

/* ---------------- main kernel ------------------------------------------- */
__global__ void __launch_bounds__(NTHREADS, 1)
mlp_kernel(const float* __restrict__ aev,
           const float* __restrict__ b1, const float* __restrict__ b2,
           const float* __restrict__ b3,
           const float* __restrict__ W4, const float* __restrict__ b4)
{
    const int s = blockIdx.y;
    const int tile0 = blockIdx.x * TILE_M;
    const int cnt = g_counts[s];
    if (tile0 >= cnt) return;

    extern __shared__ char smem[];
    const uint32_t smb = smem_u32(smem);
    const int tid = threadIdx.x;
    const int lane = tid & 31, wid = tid >> 5;
    int* s_idx = (int*)(smem + SIDX);

    if (tid < TILE_M)
        s_idx[tid] = (tile0 + tid < cnt) ? g_lists[s * NATOMS + tile0 + tid] : -1;
    __syncthreads();

    /* prefetch L1 weight chunks 0,1 (overlaps with gather below) */
    const __half* W1f = g_w + W_OFF1 + (size_t)s * N1 * K1;
    {
        const int wn = wid >> 1;
        stage_w<K1>(smb, W1f, wn, wn + 8, 2, lane, 0, 0); CP_COMMIT();
        stage_w<K1>(smb, W1f, wn, wn + 8, 2, lane, 1, 1); CP_COMMIT();
    }

    /* gather layer-1 input: 128 rows x 384 f32 -> R0 fp16 */
    for (int it = tid; it < TILE_M * 96; it += NTHREADS) {
        int r = it / 96, q = it - r * 96;
        int g = s_idx[r];
        float4 v = make_float4(0.f, 0.f, 0.f, 0.f);
        if (g >= 0) v = *(const float4*)(aev + (size_t)g * FDIM + q * 4);
        __half2 h01 = __floats2half2_rn(v.x, v.y);
        __half2 h23 = __floats2half2_rn(v.z, v.w);
        uint32_t o = swoff((uint32_t)r, (uint32_t)(q * 8), 768);
        *(uint2*)(smem + R0_OFF + o) = make_uint2(*(uint32_t*)&h01, *(uint32_t*)&h23);
    }
    __syncthreads();

    /* L1: R0(768) -> R1(512) ; weight chunks 0,1 already staged */
    {
        const int wm = wid & 1, wn = wid >> 1;
        const uint32_t lrow = (uint32_t)((lane & 7) + (lane & 8));
        const uint32_t lk   = (uint32_t)(lane >> 4);
        const float* bias = b1 + s * N1;
        constexpr int NKC = K1 / 64;

        float acc[2][4][2][4];
#pragma unroll
        for (int a = 0; a < 2; a++)
#pragma unroll
            for (int b = 0; b < 4; b++)
#pragma unroll
                for (int c = 0; c < 2; c++)
#pragma unroll
                    for (int d = 0; d < 4; d++) acc[a][b][c][d] = 0.f;

        for (int kc = 0; kc < NKC; kc++) {
            CP_WAIT1();
            __syncwarp();
            const uint32_t wb = smb + WBUF + (uint32_t)(kc & 1) * 32768u;
#pragma unroll
            for (int st = 0; st < 4; st++) {
                uint32_t af[4][4];
#pragma unroll
                for (int mt = 0; mt < 4; mt++) {
                    uint32_t r = (uint32_t)(wm * 64 + mt * 16) + lrow;
                    uint32_t kb = (uint32_t)(kc * 128 + st * 32) + lk * 16u;
                    ldsm4(af[mt], smb + R0_OFF + swoff(r, kb, 768));
                }
                uint32_t wf[2][4];
#pragma unroll
                for (int ci = 0; ci < 2; ci++) {
                    uint32_t r = (uint32_t)((ci ? wn + 8 : wn) * 16) + lrow;
                    uint32_t slot = (uint32_t)(st * 2) + lk;
                    ldsm4(wf[ci], wb + r * 128 + ((slot ^ (r & 7u)) << 4));
                }
#pragma unroll
                for (int ci = 0; ci < 2; ci++)
#pragma unroll
                    for (int mt = 0; mt < 4; mt++) {
                        mma16816(acc[ci][mt][0], af[mt], wf[ci][0], wf[ci][2]);
                        mma16816(acc[ci][mt][1], af[mt], wf[ci][1], wf[ci][3]);
                    }
            }
            PAIR_BAR(wn);
            if (kc + 2 < NKC) stage_w<K1>(smb, W1f, wn, wn + 8, 2, lane, kc + 2, kc & 1);
            CP_COMMIT();
        }
        /* epilogue -> R1 (512B rows) */
#pragma unroll
        for (int ci = 0; ci < 2; ci++) {
            const int cbase = (ci ? wn + 8 : wn) * 16;
#pragma unroll
            for (int mt = 0; mt < 4; mt++)
#pragma unroll
                for (int nt = 0; nt < 2; nt++) {
                    uint32_t r0 = (uint32_t)(wm * 64 + mt * 16 + (lane >> 2));
                    int c = cbase + nt * 8 + 2 * (lane & 3);
                    float bb0 = __ldg(bias + c), bb1 = __ldg(bias + c + 1);
                    float v0 = celu01(acc[ci][mt][nt][0] + bb0);
                    float v1 = celu01(acc[ci][mt][nt][1] + bb1);
                    float v2 = celu01(acc[ci][mt][nt][2] + bb0);
                    float v3 = celu01(acc[ci][mt][nt][3] + bb1);
                    __half2 h01 = __floats2half2_rn(v0, v1);
                    __half2 h23 = __floats2half2_rn(v2, v3);
                    *(__half2*)(smem + R1_OFF + swoff(r0,     (uint32_t)(2 * c), 512)) = h01;
                    *(__half2*)(smem + R1_OFF + swoff(r0 + 8, (uint32_t)(2 * c), 512)) = h23;
                }
        }
    }
    __syncthreads();

    /* L2: R1(512) -> R0(384) */
    mlp_layer<K2, N2, 512, 384, false>(smem, smb, R1_OFF, R0_OFF,
        g_w + W_OFF2 + (size_t)s * N2 * K2, b2 + s * N2, nullptr);
    __syncthreads();

    /* L3 + L4 fused: R0(384) -> PACC (aliases R1, now dead) */
    mlp_layer<K3, N3, 384, 0, true>(smem, smb, R0_OFF, 0,
        g_w + W_OFF3 + (size_t)s * N3 * K3, b3 + s * N3, W4 + s * N3);
    __syncthreads();

    /* final per-atom sum: 8 warp-partials per row, fixed order */
    if (tid < TILE_M) {
        const float* pacc = (const float*)(smem + PACC);
        float sum = 0.f;
#pragma unroll
        for (int j = 0; j < 8; j++) sum += pacc[tid * 8 + j];
        int g = s_idx[tid];
        if (g >= 0) g_atom_energy[g] = sum + __ldg(b4 + s);
    }
}

/* ---------------- per-molecule reduction (warp per molecule) ------------ */
__global__ void reduce_kernel(float* __restrict__ out) {
    const int wid = threadIdx.x >> 5, lane = threadIdx.x & 31;
    const int m = blockIdx.x * 8 + wid;          /* 128 blocks x 8 warps */
    float v = g_atom_energy[m * NA + lane];
    if (lane < NA - 32) v += g_atom_energy[m * NA + 32 + lane];
#pragma unroll
    for (int o = 16; o > 0; o >>= 1)
        v += __shfl_down_sync(0xffffffffu, v, o);
    if (lane == 0) out[m] = v;
}

/* ---------------- launch ------------------------------------------------ */
extern "C" void kernel_launch(void* const* d_in, const int* in_sizes, int n_in,
                              void* d_out, int out_size)
{
    const int*   species = (const int*)  d_in[0];
    const float* aev     = (const float*)d_in[1];
    const float* W1      = (const float*)d_in[2];
    const float* b1      = (const float*)d_in[3];
    const float* W2      = (const float*)d_in[4];
    const float* b2      = (const float*)d_in[5];
    const float* W3      = (const float*)d_in[6];
    const float* b3      = (const float*)d_in[7];
    const float* W4      = (const float*)d_in[8];
    const float* b4      = (const float*)d_in[9];
    float* out = (float*)d_out;

    cudaFuncSetAttribute(mlp_kernel, cudaFuncAttributeMaxDynamicSharedMemorySize, SMEM_TOTAL);

    prep_kernel<<<(W_TOTAL + 255) / 256, 256>>>(W1, W2, W3);
    zero_kernel<<<1, 32>>>();
    bucket_kernel<<<(NATOMS + 255) / 256, 256>>>(species);

    dim3 grid(NATOMS / TILE_M, NUM_SPECIES);
    mlp_kernel<<<grid, NTHREADS, SMEM_TOTAL>>>(aev, b1, b2, b3, W4, b4);

    reduce_kernel<<<BMOL / 8, 256>>>(out);
}

// round 10
// speedup vs baseline: 2.7439x; 1.0191x over previous
#include <cuda_runtime.h>
#include <cuda_fp16.h>
#include <cstdint>

#define NUM_SPECIES 7
#define BMOL 1024
#define NA 48
#define NATOMS (BMOL * NA)   /* 49152 */
#define FDIM 384
#define TILE_M 128
#define NTHREADS 512
#define MAXTILES 391

/* layer sizes */
#define N1 256
#define N2 192
#define N3 160
#define K1 384
#define K2 256
#define K3 192

#define W1_ELEMS (NUM_SPECIES * N1 * K1)
#define W2_ELEMS (NUM_SPECIES * N2 * K2)
#define W3_ELEMS (NUM_SPECIES * N3 * K3)
#define W_OFF1 0
#define W_OFF2 (W1_ELEMS)
#define W_OFF3 (W1_ELEMS + W2_ELEMS)
#define W_TOTAL (W1_ELEMS + W2_ELEMS + W3_ELEMS)

__device__ int   g_counts[NUM_SPECIES];
__device__ int   g_lists[NUM_SPECIES * NATOMS];
__device__ float g_atom_energy[NATOMS];
__device__ int2  g_tiles[MAXTILES];
__device__ int   g_ntiles;
__device__ __align__(16) __half g_w[W_TOTAL];

/* ---------------- SMEM byte offsets (total 229888) ----------------------- */
#define R0_OFF 0         /* 128 rows x 768B (384 fp16) = 98304 */
#define R1_OFF 98304     /* 128 rows x 512B = 65536; doubles as gather scratch
                            (2 x 32KB f32 ring) during the L1 k-loop; PACC in L3 */
#define PACC   R1_OFF
#define WBUF   163840    /* 2 x 32KB; row = 128B (64 k fp16), XOR swizzle */
#define SIDX   229376    /* 128 x int */
#define SMEM_TOTAL 229888

/* ---------------- PTX helpers ------------------------------------------- */
__device__ __forceinline__ uint32_t smem_u32(const void* p) {
    uint32_t a;
    asm("{ .reg .u64 t; cvta.to.shared.u64 t, %1; cvt.u32.u64 %0, t; }" : "=r"(a) : "l"(p));
    return a;
}
__device__ __forceinline__ void cp16(uint32_t dst, const void* src) {
    asm volatile("cp.async.ca.shared.global [%0], [%1], 16;" :: "r"(dst), "l"(src));
}
#define CP_COMMIT() asm volatile("cp.async.commit_group;" ::: "memory")
#define CP_WAIT1()  asm volatile("cp.async.wait_group 1;" ::: "memory")
/* pairwise barrier: the 2 warps (wm=0/1) sharing wn sync on id wn+1 */
#define PAIR_BAR(wn) asm volatile("bar.sync %0, 64;" :: "r"((wn) + 1) : "memory")

__device__ __forceinline__ void ldsm4(uint32_t (&r)[4], uint32_t a) {
    asm volatile("ldmatrix.sync.aligned.m8n8.x4.shared.b16 {%0,%1,%2,%3}, [%4];"
        : "=r"(r[0]), "=r"(r[1]), "=r"(r[2]), "=r"(r[3]) : "r"(a));
}
__device__ __forceinline__ void mma16816(float (&c)[4], const uint32_t (&a)[4],
                                         uint32_t b0, uint32_t b1) {
    asm volatile("mma.sync.aligned.m16n8k16.row.col.f32.f16.f16.f32 "
        "{%0,%1,%2,%3},{%4,%5,%6,%7},{%8,%9},{%0,%1,%2,%3};"
        : "+f"(c[0]), "+f"(c[1]), "+f"(c[2]), "+f"(c[3])
        : "r"(a[0]), "r"(a[1]), "r"(a[2]), "r"(a[3]), "r"(b0), "r"(b1));
}

/* swizzled byte offset of (row r, byte-in-row kb); rowb multiple of 128 */
__device__ __forceinline__ uint32_t swoff(uint32_t r, uint32_t kb, uint32_t rowb) {
    return r * rowb + (kb & ~127u) + ((((kb >> 4) ^ r) & 7u) << 4) + (kb & 15u);
}
__device__ __forceinline__ float celu01(float x) {
    return x > 0.f ? x : 0.1f * (__expf(10.f * x) - 1.f);
}

/* ---------------- prep / bucket / tilemap ------------------------------- */
__global__ void prep_kernel(const float* __restrict__ W1,
                            const float* __restrict__ W2,
                            const float* __restrict__ W3) {
    int i = blockIdx.x * blockDim.x + threadIdx.x;
    if (i >= W_TOTAL) return;
    float v;
    if (i < W_OFF2)      v = W1[i - W_OFF1];
    else if (i < W_OFF3) v = W2[i - W_OFF2];
    else                 v = W3[i - W_OFF3];
    g_w[i] = __float2half_rn(v);
}
__global__ void zero_kernel() { if (threadIdx.x < NUM_SPECIES) g_counts[threadIdx.x] = 0; }
__global__ void bucket_kernel(const int* __restrict__ species) {
    int i = blockIdx.x * blockDim.x + threadIdx.x;
    if (i < NATOMS) {
        int s = species[i];
        g_lists[s * NATOMS + atomicAdd(&g_counts[s], 1)] = i;
    }
}
__global__ void tilemap_kernel() {
    if (threadIdx.x == 0) {
        int t = 0;
        for (int s = 0; s < NUM_SPECIES; s++)
            for (int o = 0; o < g_counts[s]; o += TILE_M)
                g_tiles[t++] = make_int2(s, o);
        g_ntiles = t;
    }
}

/* ============ warp-private weight staging =============================== */
template<int K>
__device__ __forceinline__ void stage_w(
    uint32_t smb, const __half* __restrict__ Wf,
    int ch0, int ch1, int nown, int lane, int kcc, int buf)
{
    uint32_t wb = smb + WBUF + (uint32_t)buf * 32768u;
#pragma unroll
    for (int ci = 0; ci < 2; ci++) {
        if (ci >= nown) break;
        const int ch = ci ? ch1 : ch0;
#pragma unroll
        for (int i = 0; i < 4; i++) {
            int u = lane + 32 * i;              /* 0..127 */
            int row = ch * 16 + (u >> 3);
            int slot = u & 7;
            uint32_t d = wb + (uint32_t)(row * 128 + ((slot ^ (row & 7)) << 4));
            cp16(d, Wf + (size_t)row * K + kcc * 64 + slot * 8);
        }
    }
}

/* ---------------- one MLP layer (fp16 HMMA, pair-synced k-loop) --------- */
template<int K, int N, int RIN, int ROUT, bool FUSE>
__device__ __forceinline__ void mlp_layer(
    char* smem, uint32_t smb, uint32_t IN_OFF, uint32_t OUT_OFF,
    const __half* __restrict__ Wf, const float* __restrict__ bias,
    const float* __restrict__ w4 /* only for FUSE */)
{
    const int tid = threadIdx.x;
    const int lane = tid & 31, wid = tid >> 5;
    const int wm = wid & 1, wn = wid >> 1;          /* 2 x 8 warps */
    constexpr int NKC = K / 64;
    constexpr int NCH = N / 16;

    const uint32_t lrow = (uint32_t)((lane & 7) + (lane & 8)); /* 0..15 */
    const uint32_t lk   = (uint32_t)(lane >> 4);               /* 0 / 1  */
    const int ch0 = wn, ch1 = wn + 8;
    const int nown = (ch1 < NCH) ? 2 : 1;

    stage_w<K>(smb, Wf, ch0, ch1, nown, lane, 0, 0); CP_COMMIT();
    stage_w<K>(smb, Wf, ch0, ch1, nown, lane, 1, 1); CP_COMMIT();

    float acc[2][4][2][4];   /* [chunk][mt][nt][frag] */
#pragma unroll
    for (int a = 0; a < 2; a++)
#pragma unroll
        for (int b = 0; b < 4; b++)
#pragma unroll
            for (int c = 0; c < 2; c++)
#pragma unroll
                for (int d = 0; d < 4; d++) acc[a][b][c][d] = 0.f;

    for (int kc = 0; kc < NKC; kc++) {
        CP_WAIT1();
        __syncwarp();
        const uint32_t wb = smb + WBUF + (uint32_t)(kc & 1) * 32768u;
#pragma unroll
        for (int s = 0; s < 4; s++) {               /* four k16 steps */
            uint32_t af[4][4];
#pragma unroll
            for (int mt = 0; mt < 4; mt++) {
                uint32_t r = (uint32_t)(wm * 64 + mt * 16) + lrow;
                uint32_t kb = (uint32_t)(kc * 128 + s * 32) + lk * 16u;
                ldsm4(af[mt], smb + IN_OFF + swoff(r, kb, RIN));
            }
            uint32_t wf[2][4];
#pragma unroll
            for (int ci = 0; ci < 2; ci++) {
                if (ci >= nown) break;
                uint32_t r = (uint32_t)((ci ? ch1 : ch0) * 16) + lrow;
                uint32_t slot = (uint32_t)(s * 2) + lk;
                ldsm4(wf[ci], wb + r * 128 + ((slot ^ (r & 7u)) << 4));
            }
#pragma unroll
            for (int ci = 0; ci < 2; ci++) {
                if (ci >= nown) break;
#pragma unroll
                for (int mt = 0; mt < 4; mt++) {
                    mma16816(acc[ci][mt][0], af[mt], wf[ci][0], wf[ci][2]);
                    mma16816(acc[ci][mt][1], af[mt], wf[ci][1], wf[ci][3]);
                }
            }
        }
        PAIR_BAR(wn);
        if (kc + 2 < NKC) stage_w<K>(smb, Wf, ch0, ch1, nown, lane, kc + 2, kc & 1);
        CP_COMMIT();
    }

    if (!FUSE) {
#pragma unroll
        for (int ci = 0; ci < 2; ci++) {
            if (ci >= nown) break;
            const int cbase = (ci ? ch1 : ch0) * 16;
#pragma unroll
            for (int mt = 0; mt < 4; mt++)
#pragma unroll
                for (int nt = 0; nt < 2; nt++) {
                    uint32_t r0 = (uint32_t)(wm * 64 + mt * 16 + (lane >> 2));
                    int c = cbase + nt * 8 + 2 * (lane & 3);
                    float b0 = __ldg(bias + c), b1 = __ldg(bias + c + 1);
                    float v0 = celu01(acc[ci][mt][nt][0] + b0);
                    float v1 = celu01(acc[ci][mt][nt][1] + b1);
                    float v2 = celu01(acc[ci][mt][nt][2] + b0);
                    float v3 = celu01(acc[ci][mt][nt][3] + b1);
                    __half2 h01 = __floats2half2_rn(v0, v1);
                    __half2 h23 = __floats2half2_rn(v2, v3);
                    *(__half2*)(smem + OUT_OFF + swoff(r0,     (uint32_t)(2 * c), ROUT)) = h01;
                    *(__half2*)(smem + OUT_OFF + swoff(r0 + 8, (uint32_t)(2 * c), ROUT)) = h23;
                }
        }
    } else {
        float* pacc = (float*)(smem + PACC);
#pragma unroll
        for (int mt = 0; mt < 4; mt++) {
            float p_lo = 0.f, p_hi = 0.f;
#pragma unroll
            for (int ci = 0; ci < 2; ci++) {
                if (ci >= nown) break;
                const int cbase = (ci ? ch1 : ch0) * 16;
#pragma unroll
                for (int nt = 0; nt < 2; nt++) {
                    int c = cbase + nt * 8 + 2 * (lane & 3);
                    float b0 = __ldg(bias + c), b1 = __ldg(bias + c + 1);
                    float w0 = __ldg(w4 + c),   w1 = __ldg(w4 + c + 1);
                    p_lo += celu01(acc[ci][mt][nt][0] + b0) * w0
                          + celu01(acc[ci][mt][nt][1] + b1) * w1;
                    p_hi += celu01(acc[ci][mt][nt][2] + b0) * w0
                          + celu01(acc[ci][mt][nt][3] + b1) * w1;
                }
            }
            p_lo += __shfl_xor_sync(0xffffffffu, p_lo, 1);
            p_lo += __shfl_xor_sync(0xffffffffu, p_lo, 2);
            p_hi += __shfl_xor_sync(0xffffffffu, p_hi, 1);
            p_hi += __shfl_xor_sync(0xffffffffu, p_hi, 2);
            if ((lane & 3) == 0) {
                int r0 = wm * 64 + mt * 16 + (lane >> 2);
                pacc[r0 * 8 + wn] = p_lo;
                pacc[(r0 + 8) * 8 + wn] = p_hi;
            }
        }
    }
}

/* ---------------- main kernel ------------------------------------------- */
__global__ void __launch_bounds__(NTHREADS, 1)
mlp_kernel(const float* __restrict__ aev,
           const float* __restrict__ b1, const float* __restrict__ b2,
           const float* __restrict__ b3,
           const float* __restrict__ W4, const float* __restrict__ b4)
{
    const int bid = blockIdx.x;
    if (bid >= g_ntiles) return;
    const int s = g_tiles[bid].x;
    const int tile0 = g_tiles[bid].y;
    const int cnt = g_counts[s];

    extern __shared__ char smem[];
    const uint32_t smb = smem_u32(smem);
    const int tid = threadIdx.x;
    const int lane = tid & 31, wid = tid >> 5;
    int* s_idx = (int*)(smem + SIDX);

    if (tid < TILE_M)
        s_idx[tid] = (tile0 + tid < cnt) ? g_lists[s * NATOMS + tile0 + tid] : -1;
    __syncthreads();

    /* per-thread gather sources: 4 fixed (row, slot) regions per 64-k chunk */
    const float* gsrc[4];
#pragma unroll
    for (int j = 0; j < 4; j++) {
        int u = tid + j * NTHREADS;             /* 0..2047 */
        int r = u >> 4, slot = u & 15;
        int g = s_idx[r]; if (g < 0) g = 0;     /* pad rows read atom 0; discarded */
        gsrc[j] = aev + (size_t)g * FDIM + slot * 4;
    }

    const __half* W1f = g_w + W_OFF1 + (size_t)s * N1 * K1;
    const int wm = wid & 1, wn = wid >> 1;
    const uint32_t lrow = (uint32_t)((lane & 7) + (lane & 8));
    const uint32_t lk   = (uint32_t)(lane >> 4);

    /* gather-stage: cp.async 64-k f32 slab -> R1 scratch ring */
    auto stage_g = [&](int kcc, int buf) {
        uint32_t gb = smb + R1_OFF + (uint32_t)buf * 32768u;
#pragma unroll
        for (int j = 0; j < 4; j++)
            cp16(gb + (uint32_t)(tid + j * NTHREADS) * 16u, gsrc[j] + kcc * 64);
    };

    /* L1 prologue: chunk groups carry BOTH W tile and aev slab */
    stage_w<K1>(smb, W1f, wn, wn + 8, 2, lane, 0, 0); stage_g(0, 0); CP_COMMIT();
    stage_w<K1>(smb, W1f, wn, wn + 8, 2, lane, 1, 1); stage_g(1, 1); CP_COMMIT();

    /* L1: aev(f32, streamed) -> R1(512B rows) */
    {
        const float* bias = b1 + s * N1;
        constexpr int NKC = K1 / 64;

        float acc[2][4][2][4];
#pragma unroll
        for (int a = 0; a < 2; a++)
#pragma unroll
            for (int b = 0; b < 4; b++)
#pragma unroll
                for (int c = 0; c < 2; c++)
#pragma unroll
                    for (int d = 0; d < 4; d++) acc[a][b][c][d] = 0.f;

        for (int kc = 0; kc < NKC; kc++) {
            CP_WAIT1();
            __syncwarp();
            /* convert self-copied f32 regions -> swizzled fp16 R0 chunk kc */
            {
                uint32_t gb = smb + R1_OFF + (uint32_t)(kc & 1) * 32768u;
#pragma unroll
                for (int j = 0; j < 4; j++) {
                    int u = tid + j * NTHREADS;
                    int r = u >> 4, slot = u & 15;
                    float4 v = *(const float4*)(smem + (gb - smb) + (uint32_t)u * 16u);
                    __half2 h01 = __floats2half2_rn(v.x, v.y);
                    __half2 h23 = __floats2half2_rn(v.z, v.w);
                    *(uint2*)(smem + R0_OFF + swoff((uint32_t)r,
                        (uint32_t)(kc * 128 + slot * 8), 768)) =
                        make_uint2(*(uint32_t*)&h01, *(uint32_t*)&h23);
                }
            }
            __syncthreads();   /* publish converted A chunk to all warps */

            const uint32_t wb = smb + WBUF + (uint32_t)(kc & 1) * 32768u;
#pragma unroll
            for (int st = 0; st < 4; st++) {
                uint32_t af[4][4];
#pragma unroll
                for (int mt = 0; mt < 4; mt++) {
                    uint32_t r = (uint32_t)(wm * 64 + mt * 16) + lrow;
                    uint32_t kb = (uint32_t)(kc * 128 + st * 32) + lk * 16u;
                    ldsm4(af[mt], smb + R0_OFF + swoff(r, kb, 768));
                }
                uint32_t wf[2][4];
#pragma unroll
                for (int ci = 0; ci < 2; ci++) {
                    uint32_t r = (uint32_t)((ci ? wn + 8 : wn) * 16) + lrow;
                    uint32_t slot = (uint32_t)(st * 2) + lk;
                    ldsm4(wf[ci], wb + r * 128 + ((slot ^ (r & 7u)) << 4));
                }
#pragma unroll
                for (int ci = 0; ci < 2; ci++)
#pragma unroll
                    for (int mt = 0; mt < 4; mt++) {
                        mma16816(acc[ci][mt][0], af[mt], wf[ci][0], wf[ci][2]);
                        mma16816(acc[ci][mt][1], af[mt], wf[ci][1], wf[ci][3]);
                    }
            }
            PAIR_BAR(wn);
            if (kc + 2 < NKC) {
                stage_w<K1>(smb, W1f, wn, wn + 8, 2, lane, kc + 2, kc & 1);
                stage_g(kc + 2, kc & 1);
            }
            CP_COMMIT();
        }
        __syncthreads();   /* all scratch reads done before epilogue writes R1 */
        /* epilogue -> R1 (512B rows) */
#pragma unroll
        for (int ci = 0; ci < 2; ci++) {
            const int cbase = (ci ? wn + 8 : wn) * 16;
#pragma unroll
            for (int mt = 0; mt < 4; mt++)
#pragma unroll
                for (int nt = 0; nt < 2; nt++) {
                    uint32_t r0 = (uint32_t)(wm * 64 + mt * 16 + (lane >> 2));
                    int c = cbase + nt * 8 + 2 * (lane & 3);
                    float bb0 = __ldg(bias + c), bb1 = __ldg(bias + c + 1);
                    float v0 = celu01(acc[ci][mt][nt][0] + bb0);
                    float v1 = celu01(acc[ci][mt][nt][1] + bb1);
                    float v2 = celu01(acc[ci][mt][nt][2] + bb0);
                    float v3 = celu01(acc[ci][mt][nt][3] + bb1);
                    __half2 h01 = __floats2half2_rn(v0, v1);
                    __half2 h23 = __floats2half2_rn(v2, v3);
                    *(__half2*)(smem + R1_OFF + swoff(r0,     (uint32_t)(2 * c), 512)) = h01;
                    *(__half2*)(smem + R1_OFF + swoff(r0 + 8, (uint32_t)(2 * c), 512)) = h23;
                }
        }
    }
    __syncthreads();

    /* L2: R1(512) -> R0(384) */
    mlp_layer<K2, N2, 512, 384, false>(smem, smb, R1_OFF, R0_OFF,
        g_w + W_OFF2 + (size_t)s * N2 * K2, b2 + s * N2, nullptr);
    __syncthreads();

    /* L3 + L4 fused: R0(384) -> PACC (aliases R1, now dead) */
    mlp_layer<K3, N3, 384, 0, true>(smem, smb, R0_OFF, 0,
        g_w + W_OFF3 + (size_t)s * N3 * K3, b3 + s * N3, W4 + s * N3);
    __syncthreads();

    /* final per-atom sum: 8 warp-partials per row, fixed order */
    if (tid < TILE_M) {
        const float* pacc = (const float*)(smem + PACC);
        float sum = 0.f;
#pragma unroll
        for (int j = 0; j < 8; j++) sum += pacc[tid * 8 + j];
        int g = s_idx[tid];
        if (g >= 0) g_atom_energy[g] = sum + __ldg(b4 + s);
    }
}

/* ---------------- per-molecule reduction (warp per molecule) ------------ */
__global__ void reduce_kernel(float* __restrict__ out) {
    const int wid = threadIdx.x >> 5, lane = threadIdx.x & 31;
    const int m = blockIdx.x * 8 + wid;          /* 128 blocks x 8 warps */
    float v = g_atom_energy[m * NA + lane];
    if (lane < NA - 32) v += g_atom_energy[m * NA + 32 + lane];
#pragma unroll
    for (int o = 16; o > 0; o >>= 1)
        v += __shfl_down_sync(0xffffffffu, v, o);
    if (lane == 0) out[m] = v;
}

/* ---------------- launch ------------------------------------------------ */
extern "C" void kernel_launch(void* const* d_in, const int* in_sizes, int n_in,
                              void* d_out, int out_size)
{
    const int*   species = (const int*)  d_in[0];
    const float* aev     = (const float*)d_in[1];
    const float* W1      = (const float*)d_in[2];
    const float* b1      = (const float*)d_in[3];
    const float* W2      = (const float*)d_in[4];
    const float* b2      = (const float*)d_in[5];
    const float* W3      = (const float*)d_in[6];
    const float* b3      = (const float*)d_in[7];
    const float* W4      = (const float*)d_in[8];
    const float* b4      = (const float*)d_in[9];
    float* out = (float*)d_out;

    cudaFuncSetAttribute(mlp_kernel, cudaFuncAttributeMaxDynamicSharedMemorySize, SMEM_TOTAL);

    prep_kernel<<<(W_TOTAL + 255) / 256, 256>>>(W1, W2, W3);
    zero_kernel<<<1, 32>>>();
    bucket_kernel<<<(NATOMS + 255) / 256, 256>>>(species);
    tilemap_kernel<<<1, 32>>>();

    mlp_kernel<<<MAXTILES, NTHREADS, SMEM_TOTAL>>>(aev, b1, b2, b3, W4, b4);

    reduce_kernel<<<BMOL / 8, 256>>>(out);
}

// round 14
// speedup vs baseline: 3.0037x; 1.0947x over previous
#include <cuda_runtime.h>
#include <cuda_fp16.h>
#include <cstdint>

#define NUM_SPECIES 7
#define BMOL 1024
#define NA 48
#define NATOMS (BMOL * NA)   /* 49152 */
#define FDIM 384
#define TILE_M 128
#define NTHREADS 512
#define MAXTILES 391

/* layer sizes */
#define N1 256
#define N2 192
#define N3 160
#define K1 384
#define K2 256
#define K3 192

#define W1_ELEMS (NUM_SPECIES * N1 * K1)
#define W2_ELEMS (NUM_SPECIES * N2 * K2)
#define W3_ELEMS (NUM_SPECIES * N3 * K3)
#define W_OFF1 0
#define W_OFF2 (W1_ELEMS)
#define W_OFF3 (W1_ELEMS + W2_ELEMS)
#define W_TOTAL (W1_ELEMS + W2_ELEMS + W3_ELEMS)

__device__ int   g_counts[NUM_SPECIES];
__device__ int   g_lists[NUM_SPECIES * NATOMS];
__device__ float g_atom_energy[NATOMS];
__device__ int2  g_tiles[MAXTILES];
__device__ int   g_ntiles;
__device__ __align__(16) __half g_w[W_TOTAL];

/* ---------------- SMEM byte offsets (total 229888) ----------------------- */
#define R0_OFF 0         /* 128 rows x 768B (384 fp16) = 98304 */
#define R1_OFF 98304     /* 128 rows x 512B = 65536; doubles as gather scratch
                            (2 x 32KB f32 ring) during the L1 k-loop; PACC in L3 */
#define PACC   R1_OFF
#define WBUF   163840    /* 2 x 32KB; row = 128B (64 k fp16), XOR swizzle */
#define SIDX   229376    /* 128 x int */
#define SMEM_TOTAL 229888

/* ---------------- PTX helpers ------------------------------------------- */
__device__ __forceinline__ uint32_t smem_u32(const void* p) {
    uint32_t a;
    asm("{ .reg .u64 t; cvta.to.shared.u64 t, %1; cvt.u32.u64 %0, t; }" : "=r"(a) : "l"(p));
    return a;
}
__device__ __forceinline__ void cp16(uint32_t dst, const void* src) {
    asm volatile("cp.async.ca.shared.global [%0], [%1], 16;" :: "r"(dst), "l"(src));
}
#define CP_COMMIT() asm volatile("cp.async.commit_group;" ::: "memory")
#define CP_WAIT1()  asm volatile("cp.async.wait_group 1;" ::: "memory")
/* pairwise barrier: the 2 warps (wm=0/1) sharing wn sync on id wn+1 */
#define PAIR_BAR(wn) asm volatile("bar.sync %0, 64;" :: "r"((wn) + 1) : "memory")

__device__ __forceinline__ void ldsm4(uint32_t (&r)[4], uint32_t a) {
    asm volatile("ldmatrix.sync.aligned.m8n8.x4.shared.b16 {%0,%1,%2,%3}, [%4];"
        : "=r"(r[0]), "=r"(r[1]), "=r"(r[2]), "=r"(r[3]) : "r"(a));
}
__device__ __forceinline__ void mma16816(float (&c)[4], const uint32_t (&a)[4],
                                         uint32_t b0, uint32_t b1) {
    asm volatile("mma.sync.aligned.m16n8k16.row.col.f32.f16.f16.f32 "
        "{%0,%1,%2,%3},{%4,%5,%6,%7},{%8,%9},{%0,%1,%2,%3};"
        : "+f"(c[0]), "+f"(c[1]), "+f"(c[2]), "+f"(c[3])
        : "r"(a[0]), "r"(a[1]), "r"(a[2]), "r"(a[3]), "r"(b0), "r"(b1));
}

/* swizzled byte offset of (row r, byte-in-row kb); rowb multiple of 128 */
__device__ __forceinline__ uint32_t swoff(uint32_t r, uint32_t kb, uint32_t rowb) {
    return r * rowb + (kb & ~127u) + ((((kb >> 4) ^ r) & 7u) << 4) + (kb & 15u);
}
__device__ __forceinline__ float celu01(float x) {
    return x > 0.f ? x : 0.1f * (__expf(10.f * x) - 1.f);
}

/* ---------------- prep (vectorized, + zero counts) ----------------------- */
__global__ void prep_kernel(const float* __restrict__ W1,
                            const float* __restrict__ W2,
                            const float* __restrict__ W3) {
    if (blockIdx.x == 0 && threadIdx.x < NUM_SPECIES)
        g_counts[threadIdx.x] = 0;
    int i4 = blockIdx.x * blockDim.x + threadIdx.x;
    if (i4 >= W_TOTAL / 4) return;
    int i = i4 * 4;
    const float* src;
    if (i < W_OFF2)      src = W1 + i;
    else if (i < W_OFF3) src = W2 + (i - W_OFF2);
    else                 src = W3 + (i - W_OFF3);
    float4 v = *(const float4*)src;
    __half2 a = __floats2half2_rn(v.x, v.y);
    __half2 b = __floats2half2_rn(v.z, v.w);
    *(uint2*)(g_w + i) = make_uint2(*(uint32_t*)&a, *(uint32_t*)&b);
}

/* ---------------- bucket: two-phase (shared counters) -------------------- */
__global__ void bucket_kernel(const int* __restrict__ species) {
    __shared__ int lcnt[NUM_SPECIES];
    __shared__ int lbase[NUM_SPECIES];
    const int tid = threadIdx.x;
    if (tid < NUM_SPECIES) lcnt[tid] = 0;
    __syncthreads();
    const int i = blockIdx.x * blockDim.x + tid;
    int s = -1, pos = 0;
    if (i < NATOMS) {
        s = species[i];
        pos = atomicAdd(&lcnt[s], 1);
    }
    __syncthreads();
    if (tid < NUM_SPECIES && lcnt[tid] > 0)
        lbase[tid] = atomicAdd(&g_counts[tid], lcnt[tid]);
    __syncthreads();
    if (s >= 0)
        g_lists[s * NATOMS + lbase[s] + pos] = i;
}

/* ---------------- tilemap: 7-step serial prefix + parallel fill ---------- */
__global__ void tilemap_kernel() {
    __shared__ int off[NUM_SPECIES + 1];
    const int tid = threadIdx.x;
    if (tid == 0) {
        int t = 0;
#pragma unroll
        for (int s = 0; s < NUM_SPECIES; s++) {
            off[s] = t;
            t += (g_counts[s] + TILE_M - 1) / TILE_M;
        }
        off[NUM_SPECIES] = t;
        g_ntiles = t;
    }
    __syncthreads();
    const int total = off[NUM_SPECIES];
    for (int t = tid; t < total; t += blockDim.x) {
        int s = 0;
        while (off[s + 1] <= t) s++;
        g_tiles[t] = make_int2(s, (t - off[s]) * TILE_M);
    }
}

/* ============ warp-private weight staging =============================== */
template<int K>
__device__ __forceinline__ void stage_w(
    uint32_t smb, const __half* __restrict__ Wf,
    int ch0, int ch1, int nown, int lane, int kcc, int buf)
{
    uint32_t wb = smb + WBUF + (uint32_t)buf * 32768u;
#pragma unroll
    for (int ci = 0; ci < 2; ci++) {
        if (ci >= nown) break;
        const int ch = ci ? ch1 : ch0;
#pragma unroll
        for (int i = 0; i < 4; i++) {
            int u = lane + 32 * i;              /* 0..127 */
            int row = ch * 16 + (u >> 3);
            int slot = u & 7;
            uint32_t d = wb + (uint32_t)(row * 128 + ((slot ^ (row & 7)) << 4));
            cp16(d, Wf + (size_t)row * K + kcc * 64 + slot * 8);
        }
    }
}

/* ---------------- one MLP layer (fp16 HMMA, pair-synced k-loop) --------- */
template<int K, int N, int RIN, int ROUT, bool FUSE>
__device__ __forceinline__ void mlp_layer(
    char* smem, uint32_t smb, uint32_t IN_OFF, uint32_t OUT_OFF,
    const __half* __restrict__ Wf, const float* __restrict__ bias,
    const float* __restrict__ w4 /* only for FUSE */)
{
    const int tid = threadIdx.x;
    const int lane = tid & 31, wid = tid >> 5;
    const int wm = wid & 1, wn = wid >> 1;          /* 2 x 8 warps */
    constexpr int NKC = K / 64;
    constexpr int NCH = N / 16;

    const uint32_t lrow = (uint32_t)((lane & 7) + (lane & 8)); /* 0..15 */
    const uint32_t lk   = (uint32_t)(lane >> 4);               /* 0 / 1  */
    const int ch0 = wn, ch1 = wn + 8;
    const int nown = (ch1 < NCH) ? 2 : 1;

    stage_w<K>(smb, Wf, ch0, ch1, nown, lane, 0, 0); CP_COMMIT();
    stage_w<K>(smb, Wf, ch0, ch1, nown, lane, 1, 1); CP_COMMIT();

    float acc[2][4][2][4];   /* [chunk][mt][nt][frag] */
#pragma unroll
    for (int a = 0; a < 2; a++)
#pragma unroll
        for (int b = 0; b < 4; b++)
#pragma unroll
            for (int c = 0; c < 2; c++)
#pragma unroll
                for (int d = 0; d < 4; d++) acc[a][b][c][d] = 0.f;

    for (int kc = 0; kc < NKC; kc++) {
        CP_WAIT1();
        __syncwarp();
        const uint32_t wb = smb + WBUF + (uint32_t)(kc & 1) * 32768u;
#pragma unroll
        for (int s = 0; s < 4; s++) {               /* four k16 steps */
            uint32_t af[4][4];
#pragma unroll
            for (int mt = 0; mt < 4; mt++) {
                uint32_t r = (uint32_t)(wm * 64 + mt * 16) + lrow;
                uint32_t kb = (uint32_t)(kc * 128 + s * 32) + lk * 16u;
                ldsm4(af[mt], smb + IN_OFF + swoff(r, kb, RIN));
            }
            uint32_t wf[2][4];
#pragma unroll
            for (int ci = 0; ci < 2; ci++) {
                if (ci >= nown) break;
                uint32_t r = (uint32_t)((ci ? ch1 : ch0) * 16) + lrow;
                uint32_t slot = (uint32_t)(s * 2) + lk;
                ldsm4(wf[ci], wb + r * 128 + ((slot ^ (r & 7u)) << 4));
            }
#pragma unroll
            for (int ci = 0; ci < 2; ci++) {
                if (ci >= nown) break;
#pragma unroll
                for (int mt = 0; mt < 4; mt++) {
                    mma16816(acc[ci][mt][0], af[mt], wf[ci][0], wf[ci][2]);
                    mma16816(acc[ci][mt][1], af[mt], wf[ci][1], wf[ci][3]);
                }
            }
        }
        PAIR_BAR(wn);
        if (kc + 2 < NKC) stage_w<K>(smb, Wf, ch0, ch1, nown, lane, kc + 2, kc & 1);
        CP_COMMIT();
    }

    if (!FUSE) {
#pragma unroll
        for (int ci = 0; ci < 2; ci++) {
            if (ci >= nown) break;
            const int cbase = (ci ? ch1 : ch0) * 16;
#pragma unroll
            for (int mt = 0; mt < 4; mt++)
#pragma unroll
                for (int nt = 0; nt < 2; nt++) {
                    uint32_t r0 = (uint32_t)(wm * 64 + mt * 16 + (lane >> 2));
                    int c = cbase + nt * 8 + 2 * (lane & 3);
                    float b0 = __ldg(bias + c), b1 = __ldg(bias + c + 1);
                    float v0 = celu01(acc[ci][mt][nt][0] + b0);
                    float v1 = celu01(acc[ci][mt][nt][1] + b1);
                    float v2 = celu01(acc[ci][mt][nt][2] + b0);
                    float v3 = celu01(acc[ci][mt][nt][3] + b1);
                    __half2 h01 = __floats2half2_rn(v0, v1);
                    __half2 h23 = __floats2half2_rn(v2, v3);
                    *(__half2*)(smem + OUT_OFF + swoff(r0,     (uint32_t)(2 * c), ROUT)) = h01;
                    *(__half2*)(smem + OUT_OFF + swoff(r0 + 8, (uint32_t)(2 * c), ROUT)) = h23;
                }
        }
    } else {
        float* pacc = (float*)(smem + PACC);
#pragma unroll
        for (int mt = 0; mt < 4; mt++) {
            float p_lo = 0.f, p_hi = 0.f;
#pragma unroll
            for (int ci = 0; ci < 2; ci++) {
                if (ci >= nown) break;
                const int cbase = (ci ? ch1 : ch0) * 16;
#pragma unroll
                for (int nt = 0; nt < 2; nt++) {
                    int c = cbase + nt * 8 + 2 * (lane & 3);
                    float b0 = __ldg(bias + c), b1 = __ldg(bias + c + 1);
                    float w0 = __ldg(w4 + c),   w1 = __ldg(w4 + c + 1);
                    p_lo += celu01(acc[ci][mt][nt][0] + b0) * w0
                          + celu01(acc[ci][mt][nt][1] + b1) * w1;
                    p_hi += celu01(acc[ci][mt][nt][2] + b0) * w0
                          + celu01(acc[ci][mt][nt][3] + b1) * w1;
                }
            }
            p_lo += __shfl_xor_sync(0xffffffffu, p_lo, 1);
            p_lo += __shfl_xor_sync(0xffffffffu, p_lo, 2);
            p_hi += __shfl_xor_sync(0xffffffffu, p_hi, 1);
            p_hi += __shfl_xor_sync(0xffffffffu, p_hi, 2);
            if ((lane & 3) == 0) {
                int r0 = wm * 64 + mt * 16 + (lane >> 2);
                pacc[r0 * 8 + wn] = p_lo;
                pacc[(r0 + 8) * 8 + wn] = p_hi;
            }
        }
    }
}

/* ---------------- main kernel ------------------------------------------- */
__global__ void __launch_bounds__(NTHREADS, 1)
mlp_kernel(const float* __restrict__ aev,
           const float* __restrict__ b1, const float* __restrict__ b2,
           const float* __restrict__ b3,
           const float* __restrict__ W4, const float* __restrict__ b4)
{
    const int bid = blockIdx.x;
    if (bid >= g_ntiles) return;
    const int s = g_tiles[bid].x;
    const int tile0 = g_tiles[bid].y;
    const int cnt = g_counts[s];

    extern __shared__ char smem[];
    const uint32_t smb = smem_u32(smem);
    const int tid = threadIdx.x;
    const int lane = tid & 31, wid = tid >> 5;
    int* s_idx = (int*)(smem + SIDX);

    if (tid < TILE_M)
        s_idx[tid] = (tile0 + tid < cnt) ? g_lists[s * NATOMS + tile0 + tid] : -1;
    __syncthreads();

    /* per-thread gather sources: 4 fixed (row, slot) regions per 64-k chunk */
    const float* gsrc[4];
#pragma unroll
    for (int j = 0; j < 4; j++) {
        int u = tid + j * NTHREADS;             /* 0..2047 */
        int r = u >> 4, slot = u & 15;
        int g = s_idx[r]; if (g < 0) g = 0;     /* pad rows read atom 0; discarded */
        gsrc[j] = aev + (size_t)g * FDIM + slot * 4;
    }

    const __half* W1f = g_w + W_OFF1 + (size_t)s * N1 * K1;
    const int wm = wid & 1, wn = wid >> 1;
    const uint32_t lrow = (uint32_t)((lane & 7) + (lane & 8));
    const uint32_t lk   = (uint32_t)(lane >> 4);

    /* gather-stage: cp.async 64-k f32 slab -> R1 scratch ring */
    auto stage_g = [&](int kcc, int buf) {
        uint32_t gb = smb + R1_OFF + (uint32_t)buf * 32768u;
#pragma unroll
        for (int j = 0; j < 4; j++)
            cp16(gb + (uint32_t)(tid + j * NTHREADS) * 16u, gsrc[j] + kcc * 64);
    };

    /* L1 prologue: chunk groups carry BOTH W tile and aev slab */
    stage_w<K1>(smb, W1f, wn, wn + 8, 2, lane, 0, 0); stage_g(0, 0); CP_COMMIT();
    stage_w<K1>(smb, W1f, wn, wn + 8, 2, lane, 1, 1); stage_g(1, 1); CP_COMMIT();

    /* L1: aev(f32, streamed) -> R1(512B rows) */
    {
        const float* bias = b1 + s * N1;
        constexpr int NKC = K1 / 64;

        float acc[2][4][2][4];
#pragma unroll
        for (int a = 0; a < 2; a++)
#pragma unroll
            for (int b = 0; b < 4; b++)
#pragma unroll
                for (int c = 0; c < 2; c++)
#pragma unroll
                    for (int d = 0; d < 4; d++) acc[a][b][c][d] = 0.f;

        for (int kc = 0; kc < NKC; kc++) {
            CP_WAIT1();
            __syncwarp();
            /* convert self-copied f32 regions -> swizzled fp16 R0 chunk kc */
            {
                uint32_t gb = smb + R1_OFF + (uint32_t)(kc & 1) * 32768u;
#pragma unroll
                for (int j = 0; j < 4; j++) {
                    int u = tid + j * NTHREADS;
                    int r = u >> 4, slot = u & 15;
                    float4 v = *(const float4*)(smem + (gb - smb) + (uint32_t)u * 16u);
                    __half2 h01 = __floats2half2_rn(v.x, v.y);
                    __half2 h23 = __floats2half2_rn(v.z, v.w);
                    *(uint2*)(smem + R0_OFF + swoff((uint32_t)r,
                        (uint32_t)(kc * 128 + slot * 8), 768)) =
                        make_uint2(*(uint32_t*)&h01, *(uint32_t*)&h23);
                }
            }
            __syncthreads();   /* publish converted A chunk to all warps */

            const uint32_t wb = smb + WBUF + (uint32_t)(kc & 1) * 32768u;
#pragma unroll
            for (int st = 0; st < 4; st++) {
                uint32_t af[4][4];
#pragma unroll
                for (int mt = 0; mt < 4; mt++) {
                    uint32_t r = (uint32_t)(wm * 64 + mt * 16) + lrow;
                    uint32_t kb = (uint32_t)(kc * 128 + st * 32) + lk * 16u;
                    ldsm4(af[mt], smb + R0_OFF + swoff(r, kb, 768));
                }
                uint32_t wf[2][4];
#pragma unroll
                for (int ci = 0; ci < 2; ci++) {
                    uint32_t r = (uint32_t)((ci ? wn + 8 : wn) * 16) + lrow;
                    uint32_t slot = (uint32_t)(st * 2) + lk;
                    ldsm4(wf[ci], wb + r * 128 + ((slot ^ (r & 7u)) << 4));
                }
#pragma unroll
                for (int ci = 0; ci < 2; ci++)
#pragma unroll
                    for (int mt = 0; mt < 4; mt++) {
                        mma16816(acc[ci][mt][0], af[mt], wf[ci][0], wf[ci][2]);
                        mma16816(acc[ci][mt][1], af[mt], wf[ci][1], wf[ci][3]);
                    }
            }
            PAIR_BAR(wn);
            if (kc + 2 < NKC) {
                stage_w<K1>(smb, W1f, wn, wn + 8, 2, lane, kc + 2, kc & 1);
                stage_g(kc + 2, kc & 1);
            }
            CP_COMMIT();
        }
        __syncthreads();   /* all scratch reads done before epilogue writes R1 */
        /* epilogue -> R1 (512B rows) */
#pragma unroll
        for (int ci = 0; ci < 2; ci++) {
            const int cbase = (ci ? wn + 8 : wn) * 16;
#pragma unroll
            for (int mt = 0; mt < 4; mt++)
#pragma unroll
                for (int nt = 0; nt < 2; nt++) {
                    uint32_t r0 = (uint32_t)(wm * 64 + mt * 16 + (lane >> 2));
                    int c = cbase + nt * 8 + 2 * (lane & 3);
                    float bb0 = __ldg(bias + c), bb1 = __ldg(bias + c + 1);
                    float v0 = celu01(acc[ci][mt][nt][0] + bb0);
                    float v1 = celu01(acc[ci][mt][nt][1] + bb1);
                    float v2 = celu01(acc[ci][mt][nt][2] + bb0);
                    float v3 = celu01(acc[ci][mt][nt][3] + bb1);
                    __half2 h01 = __floats2half2_rn(v0, v1);
                    __half2 h23 = __floats2half2_rn(v2, v3);
                    *(__half2*)(smem + R1_OFF + swoff(r0,     (uint32_t)(2 * c), 512)) = h01;
                    *(__half2*)(smem + R1_OFF + swoff(r0 + 8, (uint32_t)(2 * c), 512)) = h23;
                }
        }
    }
    __syncthreads();

    /* L2: R1(512) -> R0(384) */
    mlp_layer<K2, N2, 512, 384, false>(smem, smb, R1_OFF, R0_OFF,
        g_w + W_OFF2 + (size_t)s * N2 * K2, b2 + s * N2, nullptr);
    __syncthreads();

    /* L3 + L4 fused: R0(384) -> PACC (aliases R1, now dead) */
    mlp_layer<K3, N3, 384, 0, true>(smem, smb, R0_OFF, 0,
        g_w + W_OFF3 + (size_t)s * N3 * K3, b3 + s * N3, W4 + s * N3);
    __syncthreads();

    /* final per-atom sum: 8 warp-partials per row, fixed order */
    if (tid < TILE_M) {
        const float* pacc = (const float*)(smem + PACC);
        float sum = 0.f;
#pragma unroll
        for (int j = 0; j < 8; j++) sum += pacc[tid * 8 + j];
        int g = s_idx[tid];
        if (g >= 0) g_atom_energy[g] = sum + __ldg(b4 + s);
    }
}

/* ---------------- per-molecule reduction (warp per molecule) ------------ */
__global__ void reduce_kernel(float* __restrict__ out) {
    const int wid = threadIdx.x >> 5, lane = threadIdx.x & 31;
    const int m = blockIdx.x * 8 + wid;          /* 128 blocks x 8 warps */
    float v = g_atom_energy[m * NA + lane];
    if (lane < NA - 32) v += g_atom_energy[m * NA + 32 + lane];
#pragma unroll
    for (int o = 16; o > 0; o >>= 1)
        v += __shfl_down_sync(0xffffffffu, v, o);
    if (lane == 0) out[m] = v;
}

/* ---------------- launch ------------------------------------------------ */
extern "C" void kernel_launch(void* const* d_in, const int* in_sizes, int n_in,
                              void* d_out, int out_size)
{
    const int*   species = (const int*)  d_in[0];
    const float* aev     = (const float*)d_in[1];
    const float* W1      = (const float*)d_in[2];
    const float* b1      = (const float*)d_in[3];
    const float* W2      = (const float*)d_in[4];
    const float* b2      = (const float*)d_in[5];
    const float* W3      = (const float*)d_in[6];
    const float* b3      = (const float*)d_in[7];
    const float* W4      = (const float*)d_in[8];
    const float* b4      = (const float*)d_in[9];
    float* out = (float*)d_out;

    cudaFuncSetAttribute(mlp_kernel, cudaFuncAttributeMaxDynamicSharedMemorySize, SMEM_TOTAL);

    prep_kernel<<<(W_TOTAL / 4 + 255) / 256, 256>>>(W1, W2, W3);
    bucket_kernel<<<(NATOMS + 255) / 256, 256>>>(species);
    tilemap_kernel<<<1, NTHREADS>>>();

    mlp_kernel<<<MAXTILES, NTHREADS, SMEM_TOTAL>>>(aev, b1, b2, b3, W4, b4);

    reduce_kernel<<<BMOL / 8, 256>>>(out);
}

// round 16
// speedup vs baseline: 3.0111x; 1.0025x over previous
#include <cuda_runtime.h>
#include <cuda_fp16.h>
#include <cstdint>

#define NUM_SPECIES 7
#define BMOL 1024
#define NA 48
#define NATOMS (BMOL * NA)   /* 49152 */
#define FDIM 384
#define TILE_M 128
#define NTHREADS 512
#define MAXTILES 391

/* layer sizes */
#define N1 256
#define N2 192
#define N3 160
#define K1 384
#define K2 256
#define K3 192

#define W1_ELEMS (NUM_SPECIES * N1 * K1)
#define W2_ELEMS (NUM_SPECIES * N2 * K2)
#define W3_ELEMS (NUM_SPECIES * N3 * K3)
#define W_OFF1 0
#define W_OFF2 (W1_ELEMS)
#define W_OFF3 (W1_ELEMS + W2_ELEMS)
#define W_TOTAL (W1_ELEMS + W2_ELEMS + W3_ELEMS)

__device__ int   g_counts[NUM_SPECIES];
__device__ int   g_lists[NUM_SPECIES * NATOMS];
__device__ float g_atom_energy[NATOMS];
__device__ int2  g_tiles[MAXTILES];
__device__ int   g_ntiles;
__device__ __align__(16) __half g_w[W_TOTAL];

/* ---------------- SMEM byte offsets (total 229888) ----------------------- */
#define R0_OFF 0         /* 128 rows x 768B (384 fp16) = 98304 */
#define R1_OFF 98304     /* 128 rows x 512B = 65536; gather scratch in L1; PACC in L3 */
#define PACC   R1_OFF
#define WBUF   163840    /* 2 x 32KB; row = 128B (64 k fp16), XOR swizzle */
#define SIDX   229376    /* 128 x int */
#define SMEM_TOTAL 229888

/* ---------------- PTX helpers ------------------------------------------- */
__device__ __forceinline__ uint32_t smem_u32(const void* p) {
    uint32_t a;
    asm("{ .reg .u64 t; cvta.to.shared.u64 t, %1; cvt.u32.u64 %0, t; }" : "=r"(a) : "l"(p));
    return a;
}
__device__ __forceinline__ void cp16(uint32_t dst, const void* src) {
    asm volatile("cp.async.ca.shared.global [%0], [%1], 16;" :: "r"(dst), "l"(src));
}
#define CP_COMMIT() asm volatile("cp.async.commit_group;" ::: "memory")
#define CP_WAIT1()  asm volatile("cp.async.wait_group 1;" ::: "memory")
/* pairwise barrier: the 2 warps (wm=0/1) sharing wn sync on id wn+1 */
#define PAIR_BAR(wn) asm volatile("bar.sync %0, 64;" :: "r"((wn) + 1) : "memory")

__device__ __forceinline__ void ldsm4(uint32_t (&r)[4], uint32_t a) {
    asm volatile("ldmatrix.sync.aligned.m8n8.x4.shared.b16 {%0,%1,%2,%3}, [%4];"
        : "=r"(r[0]), "=r"(r[1]), "=r"(r[2]), "=r"(r[3]) : "r"(a));
}
__device__ __forceinline__ void mma16816(float (&c)[4], const uint32_t (&a)[4],
                                         uint32_t b0, uint32_t b1) {
    asm volatile("mma.sync.aligned.m16n8k16.row.col.f32.f16.f16.f32 "
        "{%0,%1,%2,%3},{%4,%5,%6,%7},{%8,%9},{%0,%1,%2,%3};"
        : "+f"(c[0]), "+f"(c[1]), "+f"(c[2]), "+f"(c[3])
        : "r"(a[0]), "r"(a[1]), "r"(a[2]), "r"(a[3]), "r"(b0), "r"(b1));
}

/* swizzled byte offset of (row r, byte-in-row kb); rowb multiple of 128 */
__device__ __forceinline__ uint32_t swoff(uint32_t r, uint32_t kb, uint32_t rowb) {
    return r * rowb + (kb & ~127u) + ((((kb >> 4) ^ r) & 7u) << 4) + (kb & 15u);
}
__device__ __forceinline__ float celu01(float x) {
    return x > 0.f ? x : 0.1f * (__expf(10.f * x) - 1.f);
}

/* ---------------- prep (vectorized, + zero counts) ----------------------- */
__global__ void prep_kernel(const float* __restrict__ W1,
                            const float* __restrict__ W2,
                            const float* __restrict__ W3) {
    if (blockIdx.x == 0 && threadIdx.x < NUM_SPECIES)
        g_counts[threadIdx.x] = 0;
    int i4 = blockIdx.x * blockDim.x + threadIdx.x;
    if (i4 >= W_TOTAL / 4) return;
    int i = i4 * 4;
    const float* src;
    if (i < W_OFF2)      src = W1 + i;
    else if (i < W_OFF3) src = W2 + (i - W_OFF2);
    else                 src = W3 + (i - W_OFF3);
    float4 v = *(const float4*)src;
    __half2 a = __floats2half2_rn(v.x, v.y);
    __half2 b = __floats2half2_rn(v.z, v.w);
    *(uint2*)(g_w + i) = make_uint2(*(uint32_t*)&a, *(uint32_t*)&b);
}

/* ---------------- bucket: two-phase (shared counters) -------------------- */
__global__ void bucket_kernel(const int* __restrict__ species) {
    __shared__ int lcnt[NUM_SPECIES];
    __shared__ int lbase[NUM_SPECIES];
    const int tid = threadIdx.x;
    if (tid < NUM_SPECIES) lcnt[tid] = 0;
    __syncthreads();
    const int i = blockIdx.x * blockDim.x + tid;
    int s = -1, pos = 0;
    if (i < NATOMS) {
        s = species[i];
        pos = atomicAdd(&lcnt[s], 1);
    }
    __syncthreads();
    if (tid < NUM_SPECIES && lcnt[tid] > 0)
        lbase[tid] = atomicAdd(&g_counts[tid], lcnt[tid]);
    __syncthreads();
    if (s >= 0)
        g_lists[s * NATOMS + lbase[s] + pos] = i;
}

/* ---------------- tilemap: 7-step serial prefix + parallel fill ---------- */
__global__ void tilemap_kernel() {
    __shared__ int off[NUM_SPECIES + 1];
    const int tid = threadIdx.x;
    if (tid == 0) {
        int t = 0;
#pragma unroll
        for (int s = 0; s < NUM_SPECIES; s++) {
            off[s] = t;
            t += (g_counts[s] + TILE_M - 1) / TILE_M;
        }
        off[NUM_SPECIES] = t;
        g_ntiles = t;
    }
    __syncthreads();
    const int total = off[NUM_SPECIES];
    for (int t = tid; t < total; t += blockDim.x) {
        int s = 0;
        while (off[s + 1] <= t) s++;
        g_tiles[t] = make_int2(s, (t - off[s]) * TILE_M);
    }
}

/* ============ warp-private weight staging =============================== */
template<int K>
__device__ __forceinline__ void stage_w(
    uint32_t smb, const __half* __restrict__ Wf,
    int ch0, int ch1, int nown, int lane, int kcc, int buf)
{
    uint32_t wb = smb + WBUF + (uint32_t)buf * 32768u;
#pragma unroll
    for (int ci = 0; ci < 2; ci++) {
        if (ci >= nown) break;
        const int ch = ci ? ch1 : ch0;
#pragma unroll
        for (int i = 0; i < 4; i++) {
            int u = lane + 32 * i;              /* 0..127 */
            int row = ch * 16 + (u >> 3);
            int slot = u & 7;
            uint32_t d = wb + (uint32_t)(row * 128 + ((slot ^ (row & 7)) << 4));
            cp16(d, Wf + (size_t)row * K + kcc * 64 + slot * 8);
        }
    }
}

/* ---------------- one MLP layer (fp16 HMMA, pair-synced k-loop) --------- */
/* PROLOGUE=false: first 2 weight chunks were prefetched by previous layer. */
/* KNEXT/NNEXT != 0: tail iterations prefetch next layer's chunks 0,1.      */
template<int K, int N, int RIN, int ROUT, bool FUSE, bool PROLOGUE, int KNEXT, int NNEXT>
__device__ __forceinline__ void mlp_layer(
    char* smem, uint32_t smb, uint32_t IN_OFF, uint32_t OUT_OFF,
    const __half* __restrict__ Wf, const float* __restrict__ bias,
    const float* __restrict__ w4, const __half* __restrict__ WfNext)
{
    const int tid = threadIdx.x;
    const int lane = tid & 31, wid = tid >> 5;
    const int wm = wid & 1, wn = wid >> 1;          /* 2 x 8 warps */
    constexpr int NKC = K / 64;
    constexpr int NCH = N / 16;
    static_assert(KNEXT == 0 || (NKC % 2 == 0), "prefetch parity needs even NKC");

    const uint32_t lrow = (uint32_t)((lane & 7) + (lane & 8)); /* 0..15 */
    const uint32_t lk   = (uint32_t)(lane >> 4);               /* 0 / 1  */
    const int ch0 = wn, ch1 = wn + 8;
    const int nown = (ch1 < NCH) ? 2 : 1;
    const int nown_next = (KNEXT > 0 && (wn + 8) < NNEXT / 16) ? 2 : 1;

    if (PROLOGUE) {
        stage_w<K>(smb, Wf, ch0, ch1, nown, lane, 0, 0); CP_COMMIT();
        stage_w<K>(smb, Wf, ch0, ch1, nown, lane, 1, 1); CP_COMMIT();
    }

    float acc[2][4][2][4];   /* [chunk][mt][nt][frag] */
#pragma unroll
    for (int a = 0; a < 2; a++)
#pragma unroll
        for (int b = 0; b < 4; b++)
#pragma unroll
            for (int c = 0; c < 2; c++)
#pragma unroll
                for (int d = 0; d < 4; d++) acc[a][b][c][d] = 0.f;

    for (int kc = 0; kc < NKC; kc++) {
        CP_WAIT1();
        __syncwarp();
        const uint32_t wb = smb + WBUF + (uint32_t)(kc & 1) * 32768u;
#pragma unroll
        for (int s = 0; s < 4; s++) {               /* four k16 steps */
            uint32_t af[4][4];
#pragma unroll
            for (int mt = 0; mt < 4; mt++) {
                uint32_t r = (uint32_t)(wm * 64 + mt * 16) + lrow;
                uint32_t kb = (uint32_t)(kc * 128 + s * 32) + lk * 16u;
                ldsm4(af[mt], smb + IN_OFF + swoff(r, kb, RIN));
            }
            uint32_t wf[2][4];
#pragma unroll
            for (int ci = 0; ci < 2; ci++) {
                if (ci >= nown) break;
                uint32_t r = (uint32_t)((ci ? ch1 : ch0) * 16) + lrow;
                uint32_t slot = (uint32_t)(s * 2) + lk;
                ldsm4(wf[ci], wb + r * 128 + ((slot ^ (r & 7u)) << 4));
            }
#pragma unroll
            for (int ci = 0; ci < 2; ci++) {
                if (ci >= nown) break;
#pragma unroll
                for (int mt = 0; mt < 4; mt++) {
                    mma16816(acc[ci][mt][0], af[mt], wf[ci][0], wf[ci][2]);
                    mma16816(acc[ci][mt][1], af[mt], wf[ci][1], wf[ci][3]);
                }
            }
        }
        PAIR_BAR(wn);
        if (kc + 2 < NKC) {
            stage_w<K>(smb, Wf, ch0, ch1, nown, lane, kc + 2, kc & 1);
        } else if (KNEXT > 0) {
            /* tail: prefetch next layer's chunk (kc+2-NKC) into parity buffer */
            stage_w<KNEXT>(smb, WfNext, ch0, ch1, nown_next, lane, kc + 2 - NKC, kc & 1);
        }
        CP_COMMIT();
    }

    if (!FUSE) {
#pragma unroll
        for (int ci = 0; ci < 2; ci++) {
            if (ci >= nown) break;
            const int cbase = (ci ? ch1 : ch0) * 16;
#pragma unroll
            for (int mt = 0; mt < 4; mt++)
#pragma unroll
                for (int nt = 0; nt < 2; nt++) {
                    uint32_t r0 = (uint32_t)(wm * 64 + mt * 16 + (lane >> 2));
                    int c = cbase + nt * 8 + 2 * (lane & 3);
                    float b0 = __ldg(bias + c), b1 = __ldg(bias + c + 1);
                    float v0 = celu01(acc[ci][mt][nt][0] + b0);
                    float v1 = celu01(acc[ci][mt][nt][1] + b1);
                    float v2 = celu01(acc[ci][mt][nt][2] + b0);
                    float v3 = celu01(acc[ci][mt][nt][3] + b1);
                    __half2 h01 = __floats2half2_rn(v0, v1);
                    __half2 h23 = __floats2half2_rn(v2, v3);
                    *(__half2*)(smem + OUT_OFF + swoff(r0,     (uint32_t)(2 * c), ROUT)) = h01;
                    *(__half2*)(smem + OUT_OFF + swoff(r0 + 8, (uint32_t)(2 * c), ROUT)) = h23;
                }
        }
    } else {
        float* pacc = (float*)(smem + PACC);
#pragma unroll
        for (int mt = 0; mt < 4; mt++) {
            float p_lo = 0.f, p_hi = 0.f;
#pragma unroll
            for (int ci = 0; ci < 2; ci++) {
                if (ci >= nown) break;
                const int cbase = (ci ? ch1 : ch0) * 16;
#pragma unroll
                for (int nt = 0; nt < 2; nt++) {
                    int c = cbase + nt * 8 + 2 * (lane & 3);
                    float b0 = __ldg(bias + c), b1 = __ldg(bias + c + 1);
                    float w0 = __ldg(w4 + c),   w1 = __ldg(w4 + c + 1);
                    p_lo += celu01(acc[ci][mt][nt][0] + b0) * w0
                          + celu01(acc[ci][mt][nt][1] + b1) * w1;
                    p_hi += celu01(acc[ci][mt][nt][2] + b0) * w0
                          + celu01(acc[ci][mt][nt][3] + b1) * w1;
                }
            }
            p_lo += __shfl_xor_sync(0xffffffffu, p_lo, 1);
            p_lo += __shfl_xor_sync(0xffffffffu, p_lo, 2);
            p_hi += __shfl_xor_sync(0xffffffffu, p_hi, 1);
            p_hi += __shfl_xor_sync(0xffffffffu, p_hi, 2);
            if ((lane & 3) == 0) {
                int r0 = wm * 64 + mt * 16 + (lane >> 2);
                pacc[r0 * 8 + wn] = p_lo;
                pacc[(r0 + 8) * 8 + wn] = p_hi;
            }
        }
    }
}

/* ---------------- main kernel ------------------------------------------- */
__global__ void __launch_bounds__(NTHREADS, 1)
mlp_kernel(const float* __restrict__ aev,
           const float* __restrict__ b1, const float* __restrict__ b2,
           const float* __restrict__ b3,
           const float* __restrict__ W4, const float* __restrict__ b4)
{
    const int bid = blockIdx.x;
    if (bid >= g_ntiles) return;
    const int s = g_tiles[bid].x;
    const int tile0 = g_tiles[bid].y;
    const int cnt = g_counts[s];

    extern __shared__ char smem[];
    const uint32_t smb = smem_u32(smem);
    const int tid = threadIdx.x;
    const int lane = tid & 31, wid = tid >> 5;
    int* s_idx = (int*)(smem + SIDX);

    if (tid < TILE_M)
        s_idx[tid] = (tile0 + tid < cnt) ? g_lists[s * NATOMS + tile0 + tid] : -1;
    __syncthreads();

    /* per-thread gather sources: 4 fixed (row, slot) regions per 64-k chunk */
    const float* gsrc[4];
#pragma unroll
    for (int j = 0; j < 4; j++) {
        int u = tid + j * NTHREADS;             /* 0..2047 */
        int r = u >> 4, slot = u & 15;
        int g = s_idx[r]; if (g < 0) g = 0;     /* pad rows read atom 0; discarded */
        gsrc[j] = aev + (size_t)g * FDIM + slot * 4;
    }

    const __half* W1f = g_w + W_OFF1 + (size_t)s * N1 * K1;
    const __half* W2f = g_w + W_OFF2 + (size_t)s * N2 * K2;
    const __half* W3f = g_w + W_OFF3 + (size_t)s * N3 * K3;
    const int wm = wid & 1, wn = wid >> 1;
    const uint32_t lrow = (uint32_t)((lane & 7) + (lane & 8));
    const uint32_t lk   = (uint32_t)(lane >> 4);
    const int nown2 = ((wn + 8) < N2 / 16) ? 2 : 1;   /* L2 chunk ownership */

    /* gather-stage: cp.async 64-k f32 slab -> R1 scratch ring */
    auto stage_g = [&](int kcc, int buf) {
        uint32_t gb = smb + R1_OFF + (uint32_t)buf * 32768u;
#pragma unroll
        for (int j = 0; j < 4; j++)
            cp16(gb + (uint32_t)(tid + j * NTHREADS) * 16u, gsrc[j] + kcc * 64);
    };

    /* L1 prologue: chunk groups carry BOTH W tile and aev slab */
    stage_w<K1>(smb, W1f, wn, wn + 8, 2, lane, 0, 0); stage_g(0, 0); CP_COMMIT();
    stage_w<K1>(smb, W1f, wn, wn + 8, 2, lane, 1, 1); stage_g(1, 1); CP_COMMIT();

    /* L1: aev(f32, streamed) -> R1(512B rows); tail prefetches L2 W chunks */
    {
        const float* bias = b1 + s * N1;
        constexpr int NKC = K1 / 64;   /* 6 */

        float acc[2][4][2][4];
#pragma unroll
        for (int a = 0; a < 2; a++)
#pragma unroll
            for (int b = 0; b < 4; b++)
#pragma unroll
                for (int c = 0; c < 2; c++)
#pragma unroll
                    for (int d = 0; d < 4; d++) acc[a][b][c][d] = 0.f;

        for (int kc = 0; kc < NKC; kc++) {
            CP_WAIT1();
            __syncwarp();
            /* convert self-copied f32 regions -> swizzled fp16 R0 chunk kc */
            {
                uint32_t gb = smb + R1_OFF + (uint32_t)(kc & 1) * 32768u;
#pragma unroll
                for (int j = 0; j < 4; j++) {
                    int u = tid + j * NTHREADS;
                    int r = u >> 4, slot = u & 15;
                    float4 v = *(const float4*)(smem + (gb - smb) + (uint32_t)u * 16u);
                    __half2 h01 = __floats2half2_rn(v.x, v.y);
                    __half2 h23 = __floats2half2_rn(v.z, v.w);
                    *(uint2*)(smem + R0_OFF + swoff((uint32_t)r,
                        (uint32_t)(kc * 128 + slot * 8), 768)) =
                        make_uint2(*(uint32_t*)&h01, *(uint32_t*)&h23);
                }
            }
            __syncthreads();   /* publish converted A chunk to all warps */

            const uint32_t wb = smb + WBUF + (uint32_t)(kc & 1) * 32768u;
#pragma unroll
            for (int st = 0; st < 4; st++) {
                uint32_t af[4][4];
#pragma unroll
                for (int mt = 0; mt < 4; mt++) {
                    uint32_t r = (uint32_t)(wm * 64 + mt * 16) + lrow;
                    uint32_t kb = (uint32_t)(kc * 128 + st * 32) + lk * 16u;
                    ldsm4(af[mt], smb + R0_OFF + swoff(r, kb, 768));
                }
                uint32_t wf[2][4];
#pragma unroll
                for (int ci = 0; ci < 2; ci++) {
                    uint32_t r = (uint32_t)((ci ? wn + 8 : wn) * 16) + lrow;
                    uint32_t slot = (uint32_t)(st * 2) + lk;
                    ldsm4(wf[ci], wb + r * 128 + ((slot ^ (r & 7u)) << 4));
                }
#pragma unroll
                for (int ci = 0; ci < 2; ci++)
#pragma unroll
                    for (int mt = 0; mt < 4; mt++) {
                        mma16816(acc[ci][mt][0], af[mt], wf[ci][0], wf[ci][2]);
                        mma16816(acc[ci][mt][1], af[mt], wf[ci][1], wf[ci][3]);
                    }
            }
            PAIR_BAR(wn);
            if (kc + 2 < NKC) {
                stage_w<K1>(smb, W1f, wn, wn + 8, 2, lane, kc + 2, kc & 1);
                stage_g(kc + 2, kc & 1);
            } else {
                /* tail: prefetch L2 weight chunk (kc+2-NKC) */
                stage_w<K2>(smb, W2f, wn, wn + 8, nown2, lane, kc + 2 - NKC, kc & 1);
            }
            CP_COMMIT();
        }
        __syncthreads();   /* all scratch reads done before epilogue writes R1 */
        /* epilogue -> R1 (512B rows) */
#pragma unroll
        for (int ci = 0; ci < 2; ci++) {
            const int cbase = (ci ? wn + 8 : wn) * 16;
#pragma unroll
            for (int mt = 0; mt < 4; mt++)
#pragma unroll
                for (int nt = 0; nt < 2; nt++) {
                    uint32_t r0 = (uint32_t)(wm * 64 + mt * 16 + (lane >> 2));
                    int c = cbase + nt * 8 + 2 * (lane & 3);
                    float bb0 = __ldg(bias + c), bb1 = __ldg(bias + c + 1);
                    float v0 = celu01(acc[ci][mt][nt][0] + bb0);
                    float v1 = celu01(acc[ci][mt][nt][1] + bb1);
                    float v2 = celu01(acc[ci][mt][nt][2] + bb0);
                    float v3 = celu01(acc[ci][mt][nt][3] + bb1);
                    __half2 h01 = __floats2half2_rn(v0, v1);
                    __half2 h23 = __floats2half2_rn(v2, v3);
                    *(__half2*)(smem + R1_OFF + swoff(r0,     (uint32_t)(2 * c), 512)) = h01;
                    *(__half2*)(smem + R1_OFF + swoff(r0 + 8, (uint32_t)(2 * c), 512)) = h23;
                }
        }
    }
    __syncthreads();

    /* L2: R1(512) -> R0(384); no prologue (prefetched); tail prefetches L3 */
    mlp_layer<K2, N2, 512, 384, false, false, K3, N3>(smem, smb, R1_OFF, R0_OFF,
        W2f, b2 + s * N2, nullptr, W3f);
    __syncthreads();

    /* L3 + L4 fused: R0(384) -> PACC; no prologue (prefetched) */
    mlp_layer<K3, N3, 384, 0, true, false, 0, 16>(smem, smb, R0_OFF, 0,
        W3f, b3 + s * N3, W4 + s * N3, nullptr);
    __syncthreads();

    /* final per-atom sum: 8 warp-partials per row, fixed order */
    if (tid < TILE_M) {
        const float* pacc = (const float*)(smem + PACC);
        float sum = 0.f;
#pragma unroll
        for (int j = 0; j < 8; j++) sum += pacc[tid * 8 + j];
        int g = s_idx[tid];
        if (g >= 0) g_atom_energy[g] = sum + __ldg(b4 + s);
    }
}

/* ---------------- per-molecule reduction (warp per molecule) ------------ */
__global__ void reduce_kernel(float* __restrict__ out) {
    const int wid = threadIdx.x >> 5, lane = threadIdx.x & 31;
    const int m = blockIdx.x * 8 + wid;          /* 128 blocks x 8 warps */
    float v = g_atom_energy[m * NA + lane];
    if (lane < NA - 32) v += g_atom_energy[m * NA + 32 + lane];
#pragma unroll
    for (int o = 16; o > 0; o >>= 1)
        v += __shfl_down_sync(0xffffffffu, v, o);
    if (lane == 0) out[m] = v;
}

/* ---------------- launch ------------------------------------------------ */
extern "C" void kernel_launch(void* const* d_in, const int* in_sizes, int n_in,
                              void* d_out, int out_size)
{
    const int*   species = (const int*)  d_in[0];
    const float* aev     = (const float*)d_in[1];
    const float* W1      = (const float*)d_in[2];
    const float* b1      = (const float*)d_in[3];
    const float* W2      = (const float*)d_in[4];
    const float* b2      = (const float*)d_in[5];
    const float* W3      = (const float*)d_in[6];
    const float* b3      = (const float*)d_in[7];
    const float* W4      = (const float*)d_in[8];
    const float* b4      = (const float*)d_in[9];
    float* out = (float*)d_out;

    cudaFuncSetAttribute(mlp_kernel, cudaFuncAttributeMaxDynamicSharedMemorySize, SMEM_TOTAL);

    prep_kernel<<<(W_TOTAL / 4 + 255) / 256, 256>>>(W1, W2, W3);
    bucket_kernel<<<(NATOMS + 255) / 256, 256>>>(species);
    tilemap_kernel<<<1, NTHREADS>>>();

    mlp_kernel<<<MAXTILES, NTHREADS, SMEM_TOTAL>>>(aev, b1, b2, b3, W4, b4);

    reduce_kernel<<<BMOL / 8, 256>>>(out);
}

// round 17
// speedup vs baseline: 3.3187x; 1.1022x over previous
#include <cuda_runtime.h>
#include <cuda_fp16.h>
#include <cstdint>

#define NUM_SPECIES 7
#define BMOL 1024
#define NA 48
#define NATOMS (BMOL * NA)   /* 49152 */
#define FDIM 384
#define TILE_M 128
#define NTHREADS 512
#define MAXTILES 391

/* layer sizes */
#define N1 256
#define N2 192
#define N3 160
#define K1 384
#define K2 256
#define K3 192

#define W1_ELEMS (NUM_SPECIES * N1 * K1)
#define W2_ELEMS (NUM_SPECIES * N2 * K2)
#define W3_ELEMS (NUM_SPECIES * N3 * K3)
#define W_OFF1 0
#define W_OFF2 (W1_ELEMS)
#define W_OFF3 (W1_ELEMS + W2_ELEMS)
#define W_TOTAL (W1_ELEMS + W2_ELEMS + W3_ELEMS)

__device__ int   g_counts[NUM_SPECIES];
__device__ int   g_lists[NUM_SPECIES * NATOMS];
__device__ float g_atom_energy[NATOMS];
__device__ int2  g_tiles[MAXTILES];
__device__ int   g_ntiles;
__device__ __align__(16) __half g_w[W_TOTAL];

/* ---------------- SMEM byte offsets (total 229888) ----------------------- */
#define R0_OFF 0         /* 128 rows x 768B (384 fp16) = 98304 */
#define R1_OFF 98304     /* 128 rows x 512B = 65536; gather scratch in L1; PACC in L3 */
#define PACC   R1_OFF
#define WBUF   163840    /* 2 x 32KB; row = 128B (64 k fp16), XOR swizzle */
#define SIDX   229376    /* 128 x int */
#define SMEM_TOTAL 229888

/* ---------------- PTX helpers ------------------------------------------- */
__device__ __forceinline__ uint32_t smem_u32(const void* p) {
    uint32_t a;
    asm("{ .reg .u64 t; cvta.to.shared.u64 t, %1; cvt.u32.u64 %0, t; }" : "=r"(a) : "l"(p));
    return a;
}
/* .cg: L2-cached, L1-bypassed — staged data has no intra-CTA reuse and
   would otherwise compete with LDSM for L1TEX wavefronts */
__device__ __forceinline__ void cp16(uint32_t dst, const void* src) {
    asm volatile("cp.async.cg.shared.global [%0], [%1], 16;" :: "r"(dst), "l"(src));
}
#define CP_COMMIT() asm volatile("cp.async.commit_group;" ::: "memory")
#define CP_WAIT1()  asm volatile("cp.async.wait_group 1;" ::: "memory")
/* pairwise barrier: the 2 warps (wm=0/1) sharing wn sync on id wn+1 */
#define PAIR_BAR(wn) asm volatile("bar.sync %0, 64;" :: "r"((wn) + 1) : "memory")

__device__ __forceinline__ void ldsm4(uint32_t (&r)[4], uint32_t a) {
    asm volatile("ldmatrix.sync.aligned.m8n8.x4.shared.b16 {%0,%1,%2,%3}, [%4];"
        : "=r"(r[0]), "=r"(r[1]), "=r"(r[2]), "=r"(r[3]) : "r"(a));
}
__device__ __forceinline__ void mma16816(float (&c)[4], const uint32_t (&a)[4],
                                         uint32_t b0, uint32_t b1) {
    asm volatile("mma.sync.aligned.m16n8k16.row.col.f32.f16.f16.f32 "
        "{%0,%1,%2,%3},{%4,%5,%6,%7},{%8,%9},{%0,%1,%2,%3};"
        : "+f"(c[0]), "+f"(c[1]), "+f"(c[2]), "+f"(c[3])
        : "r"(a[0]), "r"(a[1]), "r"(a[2]), "r"(a[3]), "r"(b0), "r"(b1));
}

/* swizzled byte offset of (row r, byte-in-row kb); rowb multiple of 128 */
__device__ __forceinline__ uint32_t swoff(uint32_t r, uint32_t kb, uint32_t rowb) {
    return r * rowb + (kb & ~127u) + ((((kb >> 4) ^ r) & 7u) << 4) + (kb & 15u);
}
__device__ __forceinline__ float celu01(float x) {
    return x > 0.f ? x : 0.1f * (__expf(10.f * x) - 1.f);
}

/* ---------------- prep (vectorized, + zero counts) ----------------------- */
__global__ void prep_kernel(const float* __restrict__ W1,
                            const float* __restrict__ W2,
                            const float* __restrict__ W3) {
    if (blockIdx.x == 0 && threadIdx.x < NUM_SPECIES)
        g_counts[threadIdx.x] = 0;
    int i4 = blockIdx.x * blockDim.x + threadIdx.x;
    if (i4 >= W_TOTAL / 4) return;
    int i = i4 * 4;
    const float* src;
    if (i < W_OFF2)      src = W1 + i;
    else if (i < W_OFF3) src = W2 + (i - W_OFF2);
    else                 src = W3 + (i - W_OFF3);
    float4 v = *(const float4*)src;
    __half2 a = __floats2half2_rn(v.x, v.y);
    __half2 b = __floats2half2_rn(v.z, v.w);
    *(uint2*)(g_w + i) = make_uint2(*(uint32_t*)&a, *(uint32_t*)&b);
}

/* ---------------- bucket: two-phase (shared counters) -------------------- */
__global__ void bucket_kernel(const int* __restrict__ species) {
    __shared__ int lcnt[NUM_SPECIES];
    __shared__ int lbase[NUM_SPECIES];
    const int tid = threadIdx.x;
    if (tid < NUM_SPECIES) lcnt[tid] = 0;
    __syncthreads();
    const int i = blockIdx.x * blockDim.x + tid;
    int s = -1, pos = 0;
    if (i < NATOMS) {
        s = species[i];
        pos = atomicAdd(&lcnt[s], 1);
    }
    __syncthreads();
    if (tid < NUM_SPECIES && lcnt[tid] > 0)
        lbase[tid] = atomicAdd(&g_counts[tid], lcnt[tid]);
    __syncthreads();
    if (s >= 0)
        g_lists[s * NATOMS + lbase[s] + pos] = i;
}

/* ---------------- tilemap: 7-step serial prefix + parallel fill ---------- */
__global__ void tilemap_kernel() {
    __shared__ int off[NUM_SPECIES + 1];
    const int tid = threadIdx.x;
    if (tid == 0) {
        int t = 0;
#pragma unroll
        for (int s = 0; s < NUM_SPECIES; s++) {
            off[s] = t;
            t += (g_counts[s] + TILE_M - 1) / TILE_M;
        }
        off[NUM_SPECIES] = t;
        g_ntiles = t;
    }
    __syncthreads();
    const int total = off[NUM_SPECIES];
    for (int t = tid; t < total; t += blockDim.x) {
        int s = 0;
        while (off[s + 1] <= t) s++;
        g_tiles[t] = make_int2(s, (t - off[s]) * TILE_M);
    }
}

/* ============ warp-private weight staging =============================== */
template<int K>
__device__ __forceinline__ void stage_w(
    uint32_t smb, const __half* __restrict__ Wf,
    int ch0, int ch1, int nown, int lane, int kcc, int buf)
{
    uint32_t wb = smb + WBUF + (uint32_t)buf * 32768u;
#pragma unroll
    for (int ci = 0; ci < 2; ci++) {
        if (ci >= nown) break;
        const int ch = ci ? ch1 : ch0;
#pragma unroll
        for (int i = 0; i < 4; i++) {
            int u = lane + 32 * i;              /* 0..127 */
            int row = ch * 16 + (u >> 3);
            int slot = u & 7;
            uint32_t d = wb + (uint32_t)(row * 128 + ((slot ^ (row & 7)) << 4));
            cp16(d, Wf + (size_t)row * K + kcc * 64 + slot * 8);
        }
    }
}

/* ---------------- one MLP layer (fp16 HMMA, pair-synced k-loop) --------- */
/* PROLOGUE=false: first 2 weight chunks were prefetched by previous layer. */
/* KNEXT/NNEXT != 0: tail iterations prefetch next layer's chunks 0,1.      */
template<int K, int N, int RIN, int ROUT, bool FUSE, bool PROLOGUE, int KNEXT, int NNEXT>
__device__ __forceinline__ void mlp_layer(
    char* smem, uint32_t smb, uint32_t IN_OFF, uint32_t OUT_OFF,
    const __half* __restrict__ Wf, const float* __restrict__ bias,
    const float* __restrict__ w4, const __half* __restrict__ WfNext)
{
    const int tid = threadIdx.x;
    const int lane = tid & 31, wid = tid >> 5;
    const int wm = wid & 1, wn = wid >> 1;          /* 2 x 8 warps */
    constexpr int NKC = K / 64;
    constexpr int NCH = N / 16;
    static_assert(KNEXT == 0 || (NKC % 2 == 0), "prefetch parity needs even NKC");

    const uint32_t lrow = (uint32_t)((lane & 7) + (lane & 8)); /* 0..15 */
    const uint32_t lk   = (uint32_t)(lane >> 4);               /* 0 / 1  */
    const int ch0 = wn, ch1 = wn + 8;
    const int nown = (ch1 < NCH) ? 2 : 1;
    const int nown_next = (KNEXT > 0 && (wn + 8) < NNEXT / 16) ? 2 : 1;

    if (PROLOGUE) {
        stage_w<K>(smb, Wf, ch0, ch1, nown, lane, 0, 0); CP_COMMIT();
        stage_w<K>(smb, Wf, ch0, ch1, nown, lane, 1, 1); CP_COMMIT();
    }

    float acc[2][4][2][4];   /* [chunk][mt][nt][frag] */
#pragma unroll
    for (int a = 0; a < 2; a++)
#pragma unroll
        for (int b = 0; b < 4; b++)
#pragma unroll
            for (int c = 0; c < 2; c++)
#pragma unroll
                for (int d = 0; d < 4; d++) acc[a][b][c][d] = 0.f;

    for (int kc = 0; kc < NKC; kc++) {
        CP_WAIT1();
        __syncwarp();
        const uint32_t wb = smb + WBUF + (uint32_t)(kc & 1) * 32768u;
#pragma unroll
        for (int s = 0; s < 4; s++) {               /* four k16 steps */
            uint32_t af[4][4];
#pragma unroll
            for (int mt = 0; mt < 4; mt++) {
                uint32_t r = (uint32_t)(wm * 64 + mt * 16) + lrow;
                uint32_t kb = (uint32_t)(kc * 128 + s * 32) + lk * 16u;
                ldsm4(af[mt], smb + IN_OFF + swoff(r, kb, RIN));
            }
            uint32_t wf[2][4];
#pragma unroll
            for (int ci = 0; ci < 2; ci++) {
                if (ci >= nown) break;
                uint32_t r = (uint32_t)((ci ? ch1 : ch0) * 16) + lrow;
                uint32_t slot = (uint32_t)(s * 2) + lk;
                ldsm4(wf[ci], wb + r * 128 + ((slot ^ (r & 7u)) << 4));
            }
#pragma unroll
            for (int ci = 0; ci < 2; ci++) {
                if (ci >= nown) break;
#pragma unroll
                for (int mt = 0; mt < 4; mt++) {
                    mma16816(acc[ci][mt][0], af[mt], wf[ci][0], wf[ci][2]);
                    mma16816(acc[ci][mt][1], af[mt], wf[ci][1], wf[ci][3]);
                }
            }
        }
        PAIR_BAR(wn);
        if (kc + 2 < NKC) {
            stage_w<K>(smb, Wf, ch0, ch1, nown, lane, kc + 2, kc & 1);
        } else if (KNEXT > 0) {
            /* tail: prefetch next layer's chunk (kc+2-NKC) into parity buffer */
            stage_w<KNEXT>(smb, WfNext, ch0, ch1, nown_next, lane, kc + 2 - NKC, kc & 1);
        }
        CP_COMMIT();
    }

    if (!FUSE) {
#pragma unroll
        for (int ci = 0; ci < 2; ci++) {
            if (ci >= nown) break;
            const int cbase = (ci ? ch1 : ch0) * 16;
#pragma unroll
            for (int mt = 0; mt < 4; mt++)
#pragma unroll
                for (int nt = 0; nt < 2; nt++) {
                    uint32_t r0 = (uint32_t)(wm * 64 + mt * 16 + (lane >> 2));
                    int c = cbase + nt * 8 + 2 * (lane & 3);
                    float b0 = __ldg(bias + c), b1 = __ldg(bias + c + 1);
                    float v0 = celu01(acc[ci][mt][nt][0] + b0);
                    float v1 = celu01(acc[ci][mt][nt][1] + b1);
                    float v2 = celu01(acc[ci][mt][nt][2] + b0);
                    float v3 = celu01(acc[ci][mt][nt][3] + b1);
                    __half2 h01 = __floats2half2_rn(v0, v1);
                    __half2 h23 = __floats2half2_rn(v2, v3);
                    *(__half2*)(smem + OUT_OFF + swoff(r0,     (uint32_t)(2 * c), ROUT)) = h01;
                    *(__half2*)(smem + OUT_OFF + swoff(r0 + 8, (uint32_t)(2 * c), ROUT)) = h23;
                }
        }
    } else {
        float* pacc = (float*)(smem + PACC);
#pragma unroll
        for (int mt = 0; mt < 4; mt++) {
            float p_lo = 0.f, p_hi = 0.f;
#pragma unroll
            for (int ci = 0; ci < 2; ci++) {
                if (ci >= nown) break;
                const int cbase = (ci ? ch1 : ch0) * 16;
#pragma unroll
                for (int nt = 0; nt < 2; nt++) {
                    int c = cbase + nt * 8 + 2 * (lane & 3);
                    float b0 = __ldg(bias + c), b1 = __ldg(bias + c + 1);
                    float w0 = __ldg(w4 + c),   w1 = __ldg(w4 + c + 1);
                    p_lo += celu01(acc[ci][mt][nt][0] + b0) * w0
                          + celu01(acc[ci][mt][nt][1] + b1) * w1;
                    p_hi += celu01(acc[ci][mt][nt][2] + b0) * w0
                          + celu01(acc[ci][mt][nt][3] + b1) * w1;
                }
            }
            p_lo += __shfl_xor_sync(0xffffffffu, p_lo, 1);
            p_lo += __shfl_xor_sync(0xffffffffu, p_lo, 2);
            p_hi += __shfl_xor_sync(0xffffffffu, p_hi, 1);
            p_hi += __shfl_xor_sync(0xffffffffu, p_hi, 2);
            if ((lane & 3) == 0) {
                int r0 = wm * 64 + mt * 16 + (lane >> 2);
                pacc[r0 * 8 + wn] = p_lo;
                pacc[(r0 + 8) * 8 + wn] = p_hi;
            }
        }
    }
}

/* ---------------- main kernel ------------------------------------------- */
__global__ void __launch_bounds__(NTHREADS, 1)
mlp_kernel(const float* __restrict__ aev,
           const float* __restrict__ b1, const float* __restrict__ b2,
           const float* __restrict__ b3,
           const float* __restrict__ W4, const float* __restrict__ b4)
{
    const int bid = blockIdx.x;
    if (bid >= g_ntiles) return;
    const int s = g_tiles[bid].x;
    const int tile0 = g_tiles[bid].y;
    const int cnt = g_counts[s];

    extern __shared__ char smem[];
    const uint32_t smb = smem_u32(smem);
    const int tid = threadIdx.x;
    const int lane = tid & 31, wid = tid >> 5;
    int* s_idx = (int*)(smem + SIDX);

    if (tid < TILE_M)
        s_idx[tid] = (tile0 + tid < cnt) ? g_lists[s * NATOMS + tile0 + tid] : -1;
    __syncthreads();

    /* per-thread gather sources: 4 fixed (row, slot) regions per 64-k chunk */
    const float* gsrc[4];
#pragma unroll
    for (int j = 0; j < 4; j++) {
        int u = tid + j * NTHREADS;             /* 0..2047 */
        int r = u >> 4, slot = u & 15;
        int g = s_idx[r]; if (g < 0) g = 0;     /* pad rows read atom 0; discarded */
        gsrc[j] = aev + (size_t)g * FDIM + slot * 4;
    }

    const __half* W1f = g_w + W_OFF1 + (size_t)s * N1 * K1;
    const __half* W2f = g_w + W_OFF2 + (size_t)s * N2 * K2;
    const __half* W3f = g_w + W_OFF3 + (size_t)s * N3 * K3;
    const int wm = wid & 1, wn = wid >> 1;
    const uint32_t lrow = (uint32_t)((lane & 7) + (lane & 8));
    const uint32_t lk   = (uint32_t)(lane >> 4);
    const int nown2 = ((wn + 8) < N2 / 16) ? 2 : 1;   /* L2 chunk ownership */

    /* gather-stage: cp.async 64-k f32 slab -> R1 scratch ring */
    auto stage_g = [&](int kcc, int buf) {
        uint32_t gb = smb + R1_OFF + (uint32_t)buf * 32768u;
#pragma unroll
        for (int j = 0; j < 4; j++)
            cp16(gb + (uint32_t)(tid + j * NTHREADS) * 16u, gsrc[j] + kcc * 64);
    };

    /* L1 prologue: chunk groups carry BOTH W tile and aev slab */
    stage_w<K1>(smb, W1f, wn, wn + 8, 2, lane, 0, 0); stage_g(0, 0); CP_COMMIT();
    stage_w<K1>(smb, W1f, wn, wn + 8, 2, lane, 1, 1); stage_g(1, 1); CP_COMMIT();

    /* L1: aev(f32, streamed) -> R1(512B rows); tail prefetches L2 W chunks */
    {
        const float* bias = b1 + s * N1;
        constexpr int NKC = K1 / 64;   /* 6 */

        float acc[2][4][2][4];
#pragma unroll
        for (int a = 0; a < 2; a++)
#pragma unroll
            for (int b = 0; b < 4; b++)
#pragma unroll
                for (int c = 0; c < 2; c++)
#pragma unroll
                    for (int d = 0; d < 4; d++) acc[a][b][c][d] = 0.f;

        for (int kc = 0; kc < NKC; kc++) {
            CP_WAIT1();
            __syncwarp();
            /* convert self-copied f32 regions -> swizzled fp16 R0 chunk kc */
            {
                uint32_t gb = smb + R1_OFF + (uint32_t)(kc & 1) * 32768u;
#pragma unroll
                for (int j = 0; j < 4; j++) {
                    int u = tid + j * NTHREADS;
                    int r = u >> 4, slot = u & 15;
                    float4 v = *(const float4*)(smem + (gb - smb) + (uint32_t)u * 16u);
                    __half2 h01 = __floats2half2_rn(v.x, v.y);
                    __half2 h23 = __floats2half2_rn(v.z, v.w);
                    *(uint2*)(smem + R0_OFF + swoff((uint32_t)r,
                        (uint32_t)(kc * 128 + slot * 8), 768)) =
                        make_uint2(*(uint32_t*)&h01, *(uint32_t*)&h23);
                }
            }
            __syncthreads();   /* publish converted A chunk to all warps */

            const uint32_t wb = smb + WBUF + (uint32_t)(kc & 1) * 32768u;
#pragma unroll
            for (int st = 0; st < 4; st++) {
                uint32_t af[4][4];
#pragma unroll
                for (int mt = 0; mt < 4; mt++) {
                    uint32_t r = (uint32_t)(wm * 64 + mt * 16) + lrow;
                    uint32_t kb = (uint32_t)(kc * 128 + st * 32) + lk * 16u;
                    ldsm4(af[mt], smb + R0_OFF + swoff(r, kb, 768));
                }
                uint32_t wf[2][4];
#pragma unroll
                for (int ci = 0; ci < 2; ci++) {
                    uint32_t r = (uint32_t)((ci ? wn + 8 : wn) * 16) + lrow;
                    uint32_t slot = (uint32_t)(st * 2) + lk;
                    ldsm4(wf[ci], wb + r * 128 + ((slot ^ (r & 7u)) << 4));
                }
#pragma unroll
                for (int ci = 0; ci < 2; ci++)
#pragma unroll
                    for (int mt = 0; mt < 4; mt++) {
                        mma16816(acc[ci][mt][0], af[mt], wf[ci][0], wf[ci][2]);
                        mma16816(acc[ci][mt][1], af[mt], wf[ci][1], wf[ci][3]);
                    }
            }
            PAIR_BAR(wn);
            if (kc + 2 < NKC) {
                stage_w<K1>(smb, W1f, wn, wn + 8, 2, lane, kc + 2, kc & 1);
                stage_g(kc + 2, kc & 1);
            } else {
                /* tail: prefetch L2 weight chunk (kc+2-NKC) */
                stage_w<K2>(smb, W2f, wn, wn + 8, nown2, lane, kc + 2 - NKC, kc & 1);
            }
            CP_COMMIT();
        }
        __syncthreads();   /* all scratch reads done before epilogue writes R1 */
        /* epilogue -> R1 (512B rows) */
#pragma unroll
        for (int ci = 0; ci < 2; ci++) {
            const int cbase = (ci ? wn + 8 : wn) * 16;
#pragma unroll
            for (int mt = 0; mt < 4; mt++)
#pragma unroll
                for (int nt = 0; nt < 2; nt++) {
                    uint32_t r0 = (uint32_t)(wm * 64 + mt * 16 + (lane >> 2));
                    int c = cbase + nt * 8 + 2 * (lane & 3);
                    float bb0 = __ldg(bias + c), bb1 = __ldg(bias + c + 1);
                    float v0 = celu01(acc[ci][mt][nt][0] + bb0);
                    float v1 = celu01(acc[ci][mt][nt][1] + bb1);
                    float v2 = celu01(acc[ci][mt][nt][2] + bb0);
                    float v3 = celu01(acc[ci][mt][nt][3] + bb1);
                    __half2 h01 = __floats2half2_rn(v0, v1);
                    __half2 h23 = __floats2half2_rn(v2, v3);
                    *(__half2*)(smem + R1_OFF + swoff(r0,     (uint32_t)(2 * c), 512)) = h01;
                    *(__half2*)(smem + R1_OFF + swoff(r0 + 8, (uint32_t)(2 * c), 512)) = h23;
                }
        }
    }
    __syncthreads();

    /* L2: R1(512) -> R0(384); no prologue (prefetched); tail prefetches L3 */
    mlp_layer<K2, N2, 512, 384, false, false, K3, N3>(smem, smb, R1_OFF, R0_OFF,
        W2f, b2 + s * N2, nullptr, W3f);
    __syncthreads();

    /* L3 + L4 fused: R0(384) -> PACC; no prologue (prefetched) */
    mlp_layer<K3, N3, 384, 0, true, false, 0, 16>(smem, smb, R0_OFF, 0,
        W3f, b3 + s * N3, W4 + s * N3, nullptr);
    __syncthreads();

    /* final per-atom sum: 8 warp-partials per row, fixed order */
    if (tid < TILE_M) {
        const float* pacc = (const float*)(smem + PACC);
        float sum = 0.f;
#pragma unroll
        for (int j = 0; j < 8; j++) sum += pacc[tid * 8 + j];
        int g = s_idx[tid];
        if (g >= 0) g_atom_energy[g] = sum + __ldg(b4 + s);
    }
}

/* ---------------- per-molecule reduction (warp per molecule) ------------ */
__global__ void reduce_kernel(float* __restrict__ out) {
    const int wid = threadIdx.x >> 5, lane = threadIdx.x & 31;
    const int m = blockIdx.x * 8 + wid;          /* 128 blocks x 8 warps */
    float v = g_atom_energy[m * NA + lane];
    if (lane < NA - 32) v += g_atom_energy[m * NA + 32 + lane];
#pragma unroll
    for (int o = 16; o > 0; o >>= 1)
        v += __shfl_down_sync(0xffffffffu, v, o);
    if (lane == 0) out[m] = v;
}

/* ---------------- launch ------------------------------------------------ */
extern "C" void kernel_launch(void* const* d_in, const int* in_sizes, int n_in,
                              void* d_out, int out_size)
{
    const int*   species = (const int*)  d_in[0];
    const float* aev     = (const float*)d_in[1];
    const float* W1      = (const float*)d_in[2];
    const float* b1      = (const float*)d_in[3];
    const float* W2      = (const float*)d_in[4];
    const float* b2      = (const float*)d_in[5];
    const float* W3      = (const float*)d_in[6];
    const float* b3      = (const float*)d_in[7];
    const float* W4      = (const float*)d_in[8];
    const float* b4      = (const float*)d_in[9];
    float* out = (float*)d_out;

    cudaFuncSetAttribute(mlp_kernel, cudaFuncAttributeMaxDynamicSharedMemorySize, SMEM_TOTAL);

    prep_kernel<<<(W_TOTAL / 4 + 255) / 256, 256>>>(W1, W2, W3);
    bucket_kernel<<<(NATOMS + 255) / 256, 256>>>(species);
    tilemap_kernel<<<1, NTHREADS>>>();

    mlp_kernel<<<MAXTILES, NTHREADS, SMEM_TOTAL>>>(aev, b1, b2, b3, W4, b4);

    reduce_kernel<<<BMOL / 8, 256>>>(out);
}